// round 1
// baseline (speedup 1.0000x reference)
#include <cuda_runtime.h>
#include <math.h>

// Shapes (fixed for this problem)
// B=32, LV=196, LT=40, D=512, H=8, DH=64, rows R = B*LV = 6272

// ---------------------------------------------------------------------------
// Scratch: one big __device__ buffer, sliced by offsets (no allocations).
// ---------------------------------------------------------------------------
#define OFF_SM   0u          // sent_mean        32*512
#define OFF_B2   16384u      // bias2 (per-batch conv1 bias) 32*512
#define OFF_V1   32768u      // v1               6272*512
#define OFF_QKV  3244032u    // qkv              6272*1536
#define OFF_AO   12877824u   // attention out    6272*512
#define OFF_W67  16089088u   // conv2_w @ out_proj_w  512*512
#define OFF_WQ   16351232u   // q_w @ W67        512*512
#define OFF_BQ   16613376u   // fused q bias     512
#define OFF_QL   16613888u   // QL               6272*512
#define OFF_KL   19825152u   // KL               6272*512
#define OFF_RM   23036416u   // rowmax           1024*196
#define OFF_CM   23237120u   // colmax partials  1024*4*196
#define OFF_S    24039936u   // S matrix         1024
#define TOTAL_F  24040960u

__device__ float g_buf[TOTAL_F];

// ---------------------------------------------------------------------------
// sent_mean[b,d] = (1/40) * sum_t sent_feat[b,t,d] * masks[b,t]
// ---------------------------------------------------------------------------
__global__ void sent_mean_kernel(const float* __restrict__ sentf,
                                 const float* __restrict__ masks,
                                 float* __restrict__ sm) {
    int b = blockIdx.x, d = threadIdx.x;
    float s = 0.f;
    #pragma unroll
    for (int t = 0; t < 40; t++)
        s += sentf[(b * 40 + t) * 512 + d] * masks[b * 40 + t];
    sm[b * 512 + d] = s * (1.f / 40.f);
}

// ---------------------------------------------------------------------------
// bias2[b,o] = conv1_b[o] + sum_c conv1_w[o, 512+c] * sent_mean[b,c]
// warp per output
// ---------------------------------------------------------------------------
__global__ void bias2_kernel(const float* __restrict__ conv1_w,
                             const float* __restrict__ conv1_b,
                             const float* __restrict__ sm,
                             float* __restrict__ b2) {
    int gw = (blockIdx.x * blockDim.x + threadIdx.x) >> 5;
    int lane = threadIdx.x & 31;
    int b = gw >> 9, o = gw & 511;
    const float* wrow = conv1_w + o * 1024 + 512;
    const float* srow = sm + b * 512;
    float s = 0.f;
    for (int c = lane; c < 512; c += 32) s += wrow[c] * srow[c];
    #pragma unroll
    for (int off = 16; off; off >>= 1) s += __shfl_xor_sync(0xffffffffu, s, off);
    if (lane == 0) b2[b * 512 + o] = conv1_b[o] + s;
}

// ---------------------------------------------------------------------------
// bq[q] = q_b[q] + sum_o q_w[q,o] * conv2_b[o]   (tiny)
// ---------------------------------------------------------------------------
__global__ void bq_kernel(const float* __restrict__ q_w,
                          const float* __restrict__ conv2_b,
                          const float* __restrict__ q_b,
                          float* __restrict__ bq) {
    int q = threadIdx.x;
    float s = 0.f;
    for (int o = 0; o < 512; o++) s += q_w[q * 512 + o] * conv2_b[o];
    bq[q] = q_b[q] + s;
}

// ---------------------------------------------------------------------------
// Generic fp32 GEMM, 64x64 block tile, 4x4 microtile, BK=32.
// C[M,N] = A(MxK, lda) * op(B) with:
//   BT=true : op(B)[k,n] = B[n*ldb + k]  (B is NxK row-major: "A·Bᵀ")
//   BT=false: op(B)[k,n] = B[k*ldb + n]  (B is KxN row-major: "A·B")
// MODE 0: plain.  MODE 1: + bias[n].  MODE 2: + bias[(r/196)*512 + n].
// All M,N,K are multiples of 64/32 — no bounds checks.
// ---------------------------------------------------------------------------
template<int MODE, bool BT>
__global__ void gemm64(const float* __restrict__ A, const float* __restrict__ B,
                       float* __restrict__ C, const float* __restrict__ bias,
                       int K, int lda, int ldb, int ldc) {
    __shared__ float As[32][65];
    __shared__ float Bs[32][65];
    int tid = threadIdx.x;
    int tx = tid & 15, ty = tid >> 4;
    int n0 = blockIdx.x * 64, m0 = blockIdx.y * 64;
    float acc[4][4];
    #pragma unroll
    for (int i = 0; i < 4; i++)
        #pragma unroll
        for (int j = 0; j < 4; j++) acc[i][j] = 0.f;

    for (int k0 = 0; k0 < K; k0 += 32) {
        #pragma unroll
        for (int i = 0; i < 8; i++) {
            int idx = tid + i * 256;
            int k = idx & 31, r = idx >> 5;
            As[k][r] = A[(m0 + r) * lda + k0 + k];
        }
        if (BT) {
            #pragma unroll
            for (int i = 0; i < 8; i++) {
                int idx = tid + i * 256;
                int k = idx & 31, r = idx >> 5;
                Bs[k][r] = B[(n0 + r) * ldb + k0 + k];
            }
        } else {
            #pragma unroll
            for (int i = 0; i < 8; i++) {
                int idx = tid + i * 256;
                int n = idx & 63, kk = idx >> 6;
                Bs[kk][n] = B[(k0 + kk) * ldb + n0 + n];
            }
        }
        __syncthreads();
        #pragma unroll
        for (int k = 0; k < 32; k++) {
            float ar[4], br[4];
            #pragma unroll
            for (int i = 0; i < 4; i++) ar[i] = As[k][ty * 4 + i];
            #pragma unroll
            for (int j = 0; j < 4; j++) br[j] = Bs[k][tx * 4 + j];
            #pragma unroll
            for (int i = 0; i < 4; i++)
                #pragma unroll
                for (int j = 0; j < 4; j++)
                    acc[i][j] += ar[i] * br[j];
        }
        __syncthreads();
    }
    #pragma unroll
    for (int i = 0; i < 4; i++) {
        int r = m0 + ty * 4 + i;
        #pragma unroll
        for (int j = 0; j < 4; j++) {
            int c = n0 + tx * 4 + j;
            float v = acc[i][j];
            if (MODE == 1) v += bias[c];
            if (MODE == 2) v += bias[(r / 196) * 512 + c];
            C[r * ldc + c] = v;
        }
    }
}

// ---------------------------------------------------------------------------
// Attention: one CTA per (b,h). K/V staged in padded smem, warp-per-row.
// qkv rows are 1536 wide: q at +0, k at +512, v at +1024, head offset h*64.
// ---------------------------------------------------------------------------
__global__ void attn_kernel(const float* __restrict__ qkv, float* __restrict__ out) {
    int b = blockIdx.x >> 3, h = blockIdx.x & 7;
    extern __shared__ float smem[];
    float* ks = smem;                // 196*65
    float* vs = smem + 196 * 65;     // 196*65
    float* qs = smem + 2 * 196 * 65; // 8*64
    int tid = threadIdx.x;
    const float* base = qkv + b * (196 * 1536) + h * 64;
    for (int idx = tid; idx < 196 * 64; idx += 256) {
        int m = idx >> 6, d = idx & 63;
        ks[m * 65 + d] = base[m * 1536 + 512 + d];
        vs[m * 65 + d] = base[m * 1536 + 1024 + d];
    }
    __syncthreads();
    int w = tid >> 5, lane = tid & 31;
    for (int l = w; l < 196; l += 8) {
        qs[w * 64 + lane]      = base[l * 1536 + lane];
        qs[w * 64 + lane + 32] = base[l * 1536 + lane + 32];
        __syncwarp();
        float s[7];
        #pragma unroll
        for (int j = 0; j < 7; j++) {
            int m = j * 32 + lane;
            if (m < 196) {
                float acc = 0.f;
                #pragma unroll
                for (int d = 0; d < 64; d++) acc += qs[w * 64 + d] * ks[m * 65 + d];
                s[j] = acc * 0.125f;
            } else {
                s[j] = -INFINITY;
            }
        }
        float mx = s[0];
        #pragma unroll
        for (int j = 1; j < 7; j++) mx = fmaxf(mx, s[j]);
        #pragma unroll
        for (int off = 16; off; off >>= 1) mx = fmaxf(mx, __shfl_xor_sync(0xffffffffu, mx, off));
        float sum = 0.f;
        #pragma unroll
        for (int j = 0; j < 7; j++) { s[j] = expf(s[j] - mx); sum += s[j]; }
        #pragma unroll
        for (int off = 16; off; off >>= 1) sum += __shfl_xor_sync(0xffffffffu, sum, off);
        float inv = 1.f / sum;
        float o0 = 0.f, o1 = 0.f;
        #pragma unroll
        for (int j = 0; j < 7; j++) {
            #pragma unroll
            for (int mm = 0; mm < 32; mm++) {
                int m = j * 32 + mm;
                if (m >= 196) break;   // uniform across lanes (depends on j,mm only)
                float p = __shfl_sync(0xffffffffu, s[j], mm);
                o0 += p * vs[m * 65 + lane];
                o1 += p * vs[m * 65 + lane + 32];
            }
        }
        int r = b * 196 + l;
        out[r * 512 + h * 64 + lane]      = o0 * inv;
        out[r * 512 + h * 64 + lane + 32] = o1 * inv;
        __syncwarp();
    }
}

// ---------------------------------------------------------------------------
// Pair logits: CTA = (l-tile, pair). Computes QL[a] (196x512) x KL[b]^T tilewise
// (64x64 tiles, looping 4 m-tiles), tracking running row-max (over m) and
// per-ltile col-max partials. No logits materialization, no atomics.
// ---------------------------------------------------------------------------
__global__ void pair_kernel(const float* __restrict__ QL, const float* __restrict__ KL,
                            float* __restrict__ rowmax_g, float* __restrict__ colmax_g) {
    int lt = blockIdx.x, pair = blockIdx.y;
    int a = pair >> 5, b = pair & 31;
    const float* Ap = QL + a * (196 * 512);
    const float* Bp = KL + b * (196 * 512);
    __shared__ float As[32][65];
    __shared__ float Bs[32][65];
    __shared__ float rowmax_s[64];
    __shared__ float colred[64][17];
    int tid = threadIdx.x;
    int tx = tid & 15, ty = tid >> 4;
    if (tid < 64) rowmax_s[tid] = -INFINITY;
    int l0 = lt * 64;

    for (int mt = 0; mt < 4; mt++) {
        int m0 = mt * 64;
        float acc[4][4];
        #pragma unroll
        for (int i = 0; i < 4; i++)
            #pragma unroll
            for (int j = 0; j < 4; j++) acc[i][j] = 0.f;

        for (int k0 = 0; k0 < 512; k0 += 32) {
            #pragma unroll
            for (int i = 0; i < 8; i++) {
                int idx = tid + i * 256;
                int k = idx & 31, r = idx >> 5;
                int gl = l0 + r;
                As[k][r] = (gl < 196) ? Ap[gl * 512 + k0 + k] : 0.f;
                int gm = m0 + r;
                Bs[k][r] = (gm < 196) ? Bp[gm * 512 + k0 + k] : 0.f;
            }
            __syncthreads();
            #pragma unroll
            for (int k = 0; k < 32; k++) {
                float ar[4], br[4];
                #pragma unroll
                for (int i = 0; i < 4; i++) ar[i] = As[k][ty * 4 + i];
                #pragma unroll
                for (int j = 0; j < 4; j++) br[j] = Bs[k][tx * 4 + j];
                #pragma unroll
                for (int i = 0; i < 4; i++)
                    #pragma unroll
                    for (int j = 0; j < 4; j++)
                        acc[i][j] += ar[i] * br[j];
            }
            __syncthreads();
        }

        // row maxes (over valid m in this tile), reduce across the 16 tx lanes
        #pragma unroll
        for (int i = 0; i < 4; i++) {
            float rm = -INFINITY;
            #pragma unroll
            for (int j = 0; j < 4; j++)
                if (m0 + tx * 4 + j < 196) rm = fmaxf(rm, acc[i][j]);
            #pragma unroll
            for (int off = 8; off; off >>= 1)
                rm = fmaxf(rm, __shfl_xor_sync(0xffffffffu, rm, off, 16));
            if (tx == 0) rowmax_s[ty * 4 + i] = fmaxf(rowmax_s[ty * 4 + i], rm);
        }
        // col maxes (over valid l rows of this ltile), reduce across ty via smem
        #pragma unroll
        for (int j = 0; j < 4; j++) {
            float cm = -INFINITY;
            #pragma unroll
            for (int i = 0; i < 4; i++)
                if (l0 + ty * 4 + i < 196) cm = fmaxf(cm, acc[i][j]);
            colred[tx * 4 + j][ty] = cm;
        }
        __syncthreads();
        if (tid < 64) {
            float cm = colred[tid][0];
            #pragma unroll
            for (int t = 1; t < 16; t++) cm = fmaxf(cm, colred[tid][t]);
            int gm = m0 + tid;
            if (gm < 196) colmax_g[(pair * 4 + lt) * 196 + gm] = cm;
        }
        __syncthreads();
    }
    if (tid < 64) {
        int gl = l0 + tid;
        if (gl < 196) rowmax_g[pair * 196 + gl] = rowmax_s[tid];
    }
}

// ---------------------------------------------------------------------------
// S[a,b] = 0.5 * ( sum_l rowmax + sum_m max_lt colmax ) / 196 * exp(logit_scale)
// ---------------------------------------------------------------------------
__global__ void reduce_s_kernel(const float* __restrict__ rowmax,
                                const float* __restrict__ colmax,
                                const float* __restrict__ logit_scale,
                                float* __restrict__ S) {
    int pair = blockIdx.x, tid = threadIdx.x;
    float s = 0.f;
    for (int l = tid; l < 196; l += 256) s += rowmax[pair * 196 + l];
    for (int m = tid; m < 196; m += 256) {
        const float* cp = colmax + pair * 4 * 196 + m;
        float c = cp[0];
        c = fmaxf(c, cp[196]);
        c = fmaxf(c, cp[2 * 196]);
        c = fmaxf(c, cp[3 * 196]);
        s += c;
    }
    __shared__ float red[256];
    red[tid] = s;
    __syncthreads();
    for (int st = 128; st; st >>= 1) {
        if (tid < st) red[tid] += red[tid + st];
        __syncthreads();
    }
    if (tid == 0) S[pair] = 0.5f * red[0] * (1.f / 196.f) * expf(logit_scale[0]);
}

// ---------------------------------------------------------------------------
// loss = -0.5 * mean_i [ (S[ii] - lse(row i)) + (S[ii] - lse(col i)) ]
// ---------------------------------------------------------------------------
__global__ void loss_kernel(const float* __restrict__ S, float* __restrict__ out) {
    int tid = threadIdx.x;
    int w = tid >> 5, lane = tid & 31;
    float rv = S[w * 32 + lane];
    float cv = S[lane * 32 + w];
    float rm = rv, cm = cv;
    #pragma unroll
    for (int off = 16; off; off >>= 1) {
        rm = fmaxf(rm, __shfl_xor_sync(0xffffffffu, rm, off));
        cm = fmaxf(cm, __shfl_xor_sync(0xffffffffu, cm, off));
    }
    float re = expf(rv - rm), cex = expf(cv - cm);
    #pragma unroll
    for (int off = 16; off; off >>= 1) {
        re  += __shfl_xor_sync(0xffffffffu, re, off);
        cex += __shfl_xor_sync(0xffffffffu, cex, off);
    }
    __shared__ float acc[32];
    if (lane == 0) {
        float d = S[w * 33];
        float lr = rm + logf(re);
        float lc = cm + logf(cex);
        acc[w] = (d - lr) + (d - lc);
    }
    __syncthreads();
    if (tid == 0) {
        float t = 0.f;
        for (int i = 0; i < 32; i++) t += acc[i];
        out[0] = -0.5f * t * (1.f / 32.f);
    }
}

// ---------------------------------------------------------------------------
extern "C" void kernel_launch(void* const* d_in, const int* in_sizes, int n_in,
                              void* d_out, int out_size) {
    const float* bef        = (const float*)d_in[0];
    const float* sentf      = (const float*)d_in[1];
    const float* aft        = (const float*)d_in[2];
    const float* masks      = (const float*)d_in[3];
    const float* conv1_w    = (const float*)d_in[4];
    const float* conv1_b    = (const float*)d_in[5];
    const float* in_proj_w  = (const float*)d_in[6];
    const float* out_proj_w = (const float*)d_in[7];
    const float* conv2_w    = (const float*)d_in[8];
    const float* conv2_b    = (const float*)d_in[9];
    const float* q_w        = (const float*)d_in[10];
    const float* q_b        = (const float*)d_in[11];
    const float* k_w        = (const float*)d_in[12];
    const float* k_b        = (const float*)d_in[13];
    const float* logit_scale= (const float*)d_in[14];

    float* base = nullptr;
    cudaGetSymbolAddress((void**)&base, g_buf);
    float* p_sm  = base + OFF_SM;
    float* p_b2  = base + OFF_B2;
    float* p_v1  = base + OFF_V1;
    float* p_qkv = base + OFF_QKV;
    float* p_ao  = base + OFF_AO;
    float* p_w67 = base + OFF_W67;
    float* p_wq  = base + OFF_WQ;
    float* p_bq  = base + OFF_BQ;
    float* p_ql  = base + OFF_QL;
    float* p_kl  = base + OFF_KL;
    float* p_rm  = base + OFF_RM;
    float* p_cm  = base + OFF_CM;
    float* p_S   = base + OFF_S;

    // text mean + per-batch conv1 bias
    sent_mean_kernel<<<32, 512>>>(sentf, masks, p_sm);
    bias2_kernel<<<2048, 256>>>(conv1_w, conv1_b, p_sm, p_b2);

    // v1 = bef @ conv1_w[:, :512]^T + bias2[b]   (6272x512x512)
    gemm64<2, true><<<dim3(8, 98), 256>>>(bef, conv1_w, p_v1, p_b2, 512, 512, 1024, 512);
    // qkv = v1 @ in_proj_w^T                     (6272x1536x512)
    gemm64<0, true><<<dim3(24, 98), 256>>>(p_v1, in_proj_w, p_qkv, nullptr, 512, 512, 512, 1536);

    // attention (256 heads)
    size_t attn_smem = (2 * 196 * 65 + 8 * 64) * sizeof(float);
    cudaFuncSetAttribute(attn_kernel, cudaFuncAttributeMaxDynamicSharedMemorySize, (int)attn_smem);
    attn_kernel<<<256, 256, attn_smem>>>(p_qkv, p_ao);

    // fused weights: W67 = conv2_w @ out_proj_w ; Wq = q_w @ W67 ; bq = q_b + q_w@conv2_b
    gemm64<0, false><<<dim3(8, 8), 256>>>(conv2_w, out_proj_w, p_w67, nullptr, 512, 512, 512, 512);
    gemm64<0, false><<<dim3(8, 8), 256>>>(q_w, p_w67, p_wq, nullptr, 512, 512, 512, 512);
    bq_kernel<<<1, 512>>>(q_w, conv2_b, q_b, p_bq);

    // QL = attn_o @ Wq^T + bq ; KL = aft @ k_w^T + k_b
    gemm64<1, true><<<dim3(8, 98), 256>>>(p_ao, p_wq, p_ql, p_bq, 512, 512, 512, 512);
    gemm64<1, true><<<dim3(8, 98), 256>>>(aft, k_w, p_kl, k_b, 512, 512, 512, 512);

    // pair logits + fused max reductions, then S, then loss
    pair_kernel<<<dim3(4, 1024), 256>>>(p_ql, p_kl, p_rm, p_cm);
    reduce_s_kernel<<<1024, 256>>>(p_rm, p_cm, logit_scale, p_S);
    loss_kernel<<<1, 1024>>>(p_S, (float*)d_out);
}

// round 2
// speedup vs baseline: 1.5133x; 1.5133x over previous
#include <cuda_runtime.h>
#include <math.h>

// Shapes fixed: B=32, LV=196, LT=40, D=512, H=8, DH=64, R=B*LV=6272

// ---------------------------------------------------------------------------
// Scratch buffer (device global; no allocations)
// ---------------------------------------------------------------------------
#define OFF_SM   0u
#define OFF_B2   16384u
#define OFF_V1   32768u
#define OFF_QKV  3244032u
#define OFF_AO   12877824u
#define OFF_W67  16089088u
#define OFF_WQ   16351232u
#define OFF_BQ   16613376u
#define OFF_QL   16613888u
#define OFF_KL   19825152u
#define OFF_RM   23036416u   // rowmax partials 1024*2*196
#define OFF_CM   23437824u   // colmax partials 1024*2*196
#define OFF_S    23839232u
#define TOTAL_F  23840256u

__device__ float g_buf[TOTAL_F];

// ---------------------------------------------------------------------------
__global__ void sent_mean_kernel(const float* __restrict__ sentf,
                                 const float* __restrict__ masks,
                                 float* __restrict__ sm) {
    int b = blockIdx.x, d = threadIdx.x;
    float s = 0.f;
    #pragma unroll
    for (int t = 0; t < 40; t++)
        s += sentf[(b * 40 + t) * 512 + d] * masks[b * 40 + t];
    sm[b * 512 + d] = s * (1.f / 40.f);
}

__global__ void bias2_kernel(const float* __restrict__ conv1_w,
                             const float* __restrict__ conv1_b,
                             const float* __restrict__ sm,
                             float* __restrict__ b2) {
    int gw = (blockIdx.x * blockDim.x + threadIdx.x) >> 5;
    int lane = threadIdx.x & 31;
    int b = gw >> 9, o = gw & 511;
    const float* wrow = conv1_w + o * 1024 + 512;
    const float* srow = sm + b * 512;
    float s = 0.f;
    for (int c = lane; c < 512; c += 32) s += wrow[c] * srow[c];
    #pragma unroll
    for (int off = 16; off; off >>= 1) s += __shfl_xor_sync(0xffffffffu, s, off);
    if (lane == 0) b2[b * 512 + o] = conv1_b[o] + s;
}

__global__ void bq_kernel(const float* __restrict__ q_w,
                          const float* __restrict__ conv2_b,
                          const float* __restrict__ q_b,
                          float* __restrict__ bq) {
    int q = threadIdx.x;
    float s = 0.f;
    for (int o = 0; o < 512; o++) s += q_w[q * 512 + o] * conv2_b[o];
    bq[q] = q_b[q] + s;
}

// ---------------------------------------------------------------------------
// Small fp32 GEMM (kept only for the two 512x512x512 weight fusions).
// C = A(MxK) * B(KxN), both row-major (non-transposed B).
// ---------------------------------------------------------------------------
__global__ void gemm64_nt(const float* __restrict__ A, const float* __restrict__ B,
                          float* __restrict__ C, int K, int lda, int ldb, int ldc) {
    __shared__ float As[32][65];
    __shared__ float Bs[32][65];
    int tid = threadIdx.x;
    int tx = tid & 15, ty = tid >> 4;
    int n0 = blockIdx.x * 64, m0 = blockIdx.y * 64;
    float acc[4][4] = {};
    for (int k0 = 0; k0 < K; k0 += 32) {
        #pragma unroll
        for (int i = 0; i < 8; i++) {
            int idx = tid + i * 256;
            int k = idx & 31, r = idx >> 5;
            As[k][r] = A[(m0 + r) * lda + k0 + k];
            int n = idx & 63, kk = idx >> 6;
            Bs[kk][n] = B[(k0 + kk) * ldb + n0 + n];
        }
        __syncthreads();
        #pragma unroll
        for (int k = 0; k < 32; k++) {
            float ar[4], br[4];
            #pragma unroll
            for (int i = 0; i < 4; i++) ar[i] = As[k][ty * 4 + i];
            #pragma unroll
            for (int j = 0; j < 4; j++) br[j] = Bs[k][tx * 4 + j];
            #pragma unroll
            for (int i = 0; i < 4; i++)
                #pragma unroll
                for (int j = 0; j < 4; j++) acc[i][j] += ar[i] * br[j];
        }
        __syncthreads();
    }
    #pragma unroll
    for (int i = 0; i < 4; i++)
        #pragma unroll
        for (int j = 0; j < 4; j++)
            C[(m0 + ty * 4 + i) * ldc + n0 + tx * 4 + j] = acc[i][j];
}

// ---------------------------------------------------------------------------
// Big fp32 GEMM: C[M,N] = A(MxK,row-major) * B(NxK,row-major)^T.
// 128x128 CTA tile, 8x8 microtile (split 4+4), BK=8, double-buffered smem.
// M % 128 == 0, N % 128 == 0, K % 8 == 0.
// MODE 0: plain. MODE 1: +bias[n]. MODE 2: +bias[(r/196)*512+n].
// ---------------------------------------------------------------------------
template<int MODE>
__global__ void __launch_bounds__(256) gemm128(
        const float* __restrict__ A, const float* __restrict__ B,
        float* __restrict__ C, const float* __restrict__ bias,
        int K, int lda, int ldb, int ldc) {
    __shared__ float As[2][8][132];
    __shared__ float Bs[2][8][132];
    int tid = threadIdx.x;
    int tx = tid & 15, ty = tid >> 4;
    int row = tid >> 1, seg = tid & 1;
    int m0 = blockIdx.y * 128, n0 = blockIdx.x * 128;

    const float* Abase = A + (m0 + row) * lda + seg * 4;
    const float* Bbase = B + (n0 + row) * ldb + seg * 4;

    float acc[8][8] = {};
    float4 pa = *(const float4*)Abase;
    float4 pb = *(const float4*)Bbase;
    As[0][seg * 4 + 0][row] = pa.x; As[0][seg * 4 + 1][row] = pa.y;
    As[0][seg * 4 + 2][row] = pa.z; As[0][seg * 4 + 3][row] = pa.w;
    Bs[0][seg * 4 + 0][row] = pb.x; Bs[0][seg * 4 + 1][row] = pb.y;
    Bs[0][seg * 4 + 2][row] = pb.z; Bs[0][seg * 4 + 3][row] = pb.w;
    __syncthreads();

    int NK = K >> 3;
    for (int kt = 0; kt < NK; kt++) {
        int cur = kt & 1;
        if (kt + 1 < NK) {
            pa = *(const float4*)(Abase + (kt + 1) * 8);
            pb = *(const float4*)(Bbase + (kt + 1) * 8);
        }
        #pragma unroll
        for (int k = 0; k < 8; k++) {
            float ar[8], br[8];
            *(float4*)(ar)     = *(const float4*)&As[cur][k][ty * 4];
            *(float4*)(ar + 4) = *(const float4*)&As[cur][k][64 + ty * 4];
            *(float4*)(br)     = *(const float4*)&Bs[cur][k][tx * 4];
            *(float4*)(br + 4) = *(const float4*)&Bs[cur][k][64 + tx * 4];
            #pragma unroll
            for (int i = 0; i < 8; i++)
                #pragma unroll
                for (int j = 0; j < 8; j++)
                    acc[i][j] += ar[i] * br[j];
        }
        if (kt + 1 < NK) {
            int nxt = cur ^ 1;
            As[nxt][seg * 4 + 0][row] = pa.x; As[nxt][seg * 4 + 1][row] = pa.y;
            As[nxt][seg * 4 + 2][row] = pa.z; As[nxt][seg * 4 + 3][row] = pa.w;
            Bs[nxt][seg * 4 + 0][row] = pb.x; Bs[nxt][seg * 4 + 1][row] = pb.y;
            Bs[nxt][seg * 4 + 2][row] = pb.z; Bs[nxt][seg * 4 + 3][row] = pb.w;
        }
        __syncthreads();
    }

    #pragma unroll
    for (int i = 0; i < 8; i++) {
        int r = m0 + ty * 4 + (i & 3) + ((i >> 2) << 6);
        float bb = 0.f;
        int boff = (MODE == 2) ? (r / 196) * 512 : 0;
        #pragma unroll
        for (int hj = 0; hj < 2; hj++) {
            int c = n0 + tx * 4 + (hj << 6);
            float4 v;
            v.x = acc[i][hj * 4 + 0]; v.y = acc[i][hj * 4 + 1];
            v.z = acc[i][hj * 4 + 2]; v.w = acc[i][hj * 4 + 3];
            if (MODE == 1) {
                v.x += bias[c]; v.y += bias[c + 1]; v.z += bias[c + 2]; v.w += bias[c + 3];
            }
            if (MODE == 2) {
                v.x += bias[boff + c]; v.y += bias[boff + c + 1];
                v.z += bias[boff + c + 2]; v.w += bias[boff + c + 3];
            }
            (void)bb;
            *(float4*)&C[r * ldc + c] = v;
        }
    }
}

// ---------------------------------------------------------------------------
// Attention: one CTA per (b,h).
// ---------------------------------------------------------------------------
__global__ void attn_kernel(const float* __restrict__ qkv, float* __restrict__ out) {
    int b = blockIdx.x >> 3, h = blockIdx.x & 7;
    extern __shared__ float smem[];
    float* ks = smem;
    float* vs = smem + 196 * 65;
    float* qs = smem + 2 * 196 * 65;
    int tid = threadIdx.x;
    const float* base = qkv + b * (196 * 1536) + h * 64;
    for (int idx = tid; idx < 196 * 64; idx += 256) {
        int m = idx >> 6, d = idx & 63;
        ks[m * 65 + d] = base[m * 1536 + 512 + d];
        vs[m * 65 + d] = base[m * 1536 + 1024 + d];
    }
    __syncthreads();
    int w = tid >> 5, lane = tid & 31;
    for (int l = w; l < 196; l += 8) {
        qs[w * 64 + lane]      = base[l * 1536 + lane];
        qs[w * 64 + lane + 32] = base[l * 1536 + lane + 32];
        __syncwarp();
        float s[7];
        #pragma unroll
        for (int j = 0; j < 7; j++) {
            int m = j * 32 + lane;
            if (m < 196) {
                float acc = 0.f;
                #pragma unroll
                for (int d = 0; d < 64; d++) acc += qs[w * 64 + d] * ks[m * 65 + d];
                s[j] = acc * 0.125f;
            } else s[j] = -INFINITY;
        }
        float mx = s[0];
        #pragma unroll
        for (int j = 1; j < 7; j++) mx = fmaxf(mx, s[j]);
        #pragma unroll
        for (int off = 16; off; off >>= 1) mx = fmaxf(mx, __shfl_xor_sync(0xffffffffu, mx, off));
        float sum = 0.f;
        #pragma unroll
        for (int j = 0; j < 7; j++) { s[j] = expf(s[j] - mx); sum += s[j]; }
        #pragma unroll
        for (int off = 16; off; off >>= 1) sum += __shfl_xor_sync(0xffffffffu, sum, off);
        float inv = 1.f / sum;
        float o0 = 0.f, o1 = 0.f;
        #pragma unroll
        for (int j = 0; j < 7; j++) {
            #pragma unroll
            for (int mm = 0; mm < 32; mm++) {
                int m = j * 32 + mm;
                if (m >= 196) break;
                float p = __shfl_sync(0xffffffffu, s[j], mm);
                o0 += p * vs[m * 65 + lane];
                o1 += p * vs[m * 65 + lane + 32];
            }
        }
        int r = b * 196 + l;
        out[r * 512 + h * 64 + lane]      = o0 * inv;
        out[r * 512 + h * 64 + lane + 32] = o1 * inv;
        __syncwarp();
    }
}

// ---------------------------------------------------------------------------
// Pair logits with fused row/col max. Grid (mt=2, lt=2, pair=1024).
// Each CTA: 128x128 tile of QL[a](196x512) x KL[b]^T.
// ---------------------------------------------------------------------------
__global__ void __launch_bounds__(256) pair_kernel(
        const float* __restrict__ QL, const float* __restrict__ KL,
        float* __restrict__ rowmax_g, float* __restrict__ colmax_g) {
    int mt = blockIdx.x, lt = blockIdx.y, pair = blockIdx.z;
    int a = pair >> 5, b = pair & 31;
    const float* Ap = QL + a * (196 * 512);
    const float* Bp = KL + b * (196 * 512);
    __shared__ float As[2][8][132];
    __shared__ float Bs[2][8][132];
    __shared__ float colred[128][17];
    int tid = threadIdx.x;
    int tx = tid & 15, ty = tid >> 4;
    int row = tid >> 1, seg = tid & 1;
    int l0 = lt * 128, m0 = mt * 128;
    int gla = l0 + row, gmb = m0 + row;
    const float4 zero4 = make_float4(0.f, 0.f, 0.f, 0.f);

    float acc[8][8] = {};
    float4 pa = (gla < 196) ? *(const float4*)(Ap + gla * 512 + seg * 4) : zero4;
    float4 pb = (gmb < 196) ? *(const float4*)(Bp + gmb * 512 + seg * 4) : zero4;
    As[0][seg * 4 + 0][row] = pa.x; As[0][seg * 4 + 1][row] = pa.y;
    As[0][seg * 4 + 2][row] = pa.z; As[0][seg * 4 + 3][row] = pa.w;
    Bs[0][seg * 4 + 0][row] = pb.x; Bs[0][seg * 4 + 1][row] = pb.y;
    Bs[0][seg * 4 + 2][row] = pb.z; Bs[0][seg * 4 + 3][row] = pb.w;
    __syncthreads();

    const int NK = 64;  // 512/8
    for (int kt = 0; kt < NK; kt++) {
        int cur = kt & 1;
        if (kt + 1 < NK) {
            pa = (gla < 196) ? *(const float4*)(Ap + gla * 512 + (kt + 1) * 8 + seg * 4) : zero4;
            pb = (gmb < 196) ? *(const float4*)(Bp + gmb * 512 + (kt + 1) * 8 + seg * 4) : zero4;
        }
        #pragma unroll
        for (int k = 0; k < 8; k++) {
            float ar[8], br[8];
            *(float4*)(ar)     = *(const float4*)&As[cur][k][ty * 4];
            *(float4*)(ar + 4) = *(const float4*)&As[cur][k][64 + ty * 4];
            *(float4*)(br)     = *(const float4*)&Bs[cur][k][tx * 4];
            *(float4*)(br + 4) = *(const float4*)&Bs[cur][k][64 + tx * 4];
            #pragma unroll
            for (int i = 0; i < 8; i++)
                #pragma unroll
                for (int j = 0; j < 8; j++)
                    acc[i][j] += ar[i] * br[j];
        }
        if (kt + 1 < NK) {
            int nxt = cur ^ 1;
            As[nxt][seg * 4 + 0][row] = pa.x; As[nxt][seg * 4 + 1][row] = pa.y;
            As[nxt][seg * 4 + 2][row] = pa.z; As[nxt][seg * 4 + 3][row] = pa.w;
            Bs[nxt][seg * 4 + 0][row] = pb.x; Bs[nxt][seg * 4 + 1][row] = pb.y;
            Bs[nxt][seg * 4 + 2][row] = pb.z; Bs[nxt][seg * 4 + 3][row] = pb.w;
        }
        __syncthreads();
    }

    // row maxes: for each of this thread's 8 rows, max over valid m cols,
    // then reduce across the 16 tx lanes (half-warp shfl).
    #pragma unroll
    for (int i = 0; i < 8; i++) {
        int lr = ty * 4 + (i & 3) + ((i >> 2) << 6);
        int gl = l0 + lr;
        float rm = -INFINITY;
        #pragma unroll
        for (int j = 0; j < 8; j++) {
            int lc = tx * 4 + (j & 3) + ((j >> 2) << 6);
            if (m0 + lc < 196) rm = fmaxf(rm, acc[i][j]);
        }
        #pragma unroll
        for (int off = 8; off; off >>= 1)
            rm = fmaxf(rm, __shfl_xor_sync(0xffffffffu, rm, off, 16));
        if (tx == 0 && gl < 196)
            rowmax_g[(pair * 2 + mt) * 196 + gl] = rm;
    }
    // col maxes: per col, max over this thread's valid l rows -> smem reduce over ty.
    #pragma unroll
    for (int j = 0; j < 8; j++) {
        int lc = tx * 4 + (j & 3) + ((j >> 2) << 6);
        float cm = -INFINITY;
        #pragma unroll
        for (int i = 0; i < 8; i++) {
            int lr = ty * 4 + (i & 3) + ((i >> 2) << 6);
            if (l0 + lr < 196) cm = fmaxf(cm, acc[i][j]);
        }
        colred[lc][ty] = cm;
    }
    __syncthreads();
    if (tid < 128) {
        float cm = colred[tid][0];
        #pragma unroll
        for (int t = 1; t < 16; t++) cm = fmaxf(cm, colred[tid][t]);
        int gm = m0 + tid;
        if (gm < 196) colmax_g[(pair * 2 + lt) * 196 + gm] = cm;
    }
}

// ---------------------------------------------------------------------------
__global__ void reduce_s_kernel(const float* __restrict__ rowmax,
                                const float* __restrict__ colmax,
                                const float* __restrict__ logit_scale,
                                float* __restrict__ S) {
    int pair = blockIdx.x, tid = threadIdx.x;
    float s = 0.f;
    for (int l = tid; l < 196; l += 256)
        s += fmaxf(rowmax[(pair * 2) * 196 + l], rowmax[(pair * 2 + 1) * 196 + l]);
    for (int m = tid; m < 196; m += 256)
        s += fmaxf(colmax[(pair * 2) * 196 + m], colmax[(pair * 2 + 1) * 196 + m]);
    __shared__ float red[256];
    red[tid] = s;
    __syncthreads();
    for (int st = 128; st; st >>= 1) {
        if (tid < st) red[tid] += red[tid + st];
        __syncthreads();
    }
    if (tid == 0) S[pair] = 0.5f * red[0] * (1.f / 196.f) * expf(logit_scale[0]);
}

__global__ void loss_kernel(const float* __restrict__ S, float* __restrict__ out) {
    int tid = threadIdx.x;
    int w = tid >> 5, lane = tid & 31;
    float rv = S[w * 32 + lane];
    float cv = S[lane * 32 + w];
    float rm = rv, cm = cv;
    #pragma unroll
    for (int off = 16; off; off >>= 1) {
        rm = fmaxf(rm, __shfl_xor_sync(0xffffffffu, rm, off));
        cm = fmaxf(cm, __shfl_xor_sync(0xffffffffu, cm, off));
    }
    float re = expf(rv - rm), cex = expf(cv - cm);
    #pragma unroll
    for (int off = 16; off; off >>= 1) {
        re  += __shfl_xor_sync(0xffffffffu, re, off);
        cex += __shfl_xor_sync(0xffffffffu, cex, off);
    }
    __shared__ float acc[32];
    if (lane == 0) {
        float d = S[w * 33];
        acc[w] = (d - (rm + logf(re))) + (d - (cm + logf(cex)));
    }
    __syncthreads();
    if (tid == 0) {
        float t = 0.f;
        for (int i = 0; i < 32; i++) t += acc[i];
        out[0] = -0.5f * t * (1.f / 32.f);
    }
}

// ---------------------------------------------------------------------------
extern "C" void kernel_launch(void* const* d_in, const int* in_sizes, int n_in,
                              void* d_out, int out_size) {
    const float* bef        = (const float*)d_in[0];
    const float* sentf      = (const float*)d_in[1];
    const float* aft        = (const float*)d_in[2];
    const float* masks      = (const float*)d_in[3];
    const float* conv1_w    = (const float*)d_in[4];
    const float* conv1_b    = (const float*)d_in[5];
    const float* in_proj_w  = (const float*)d_in[6];
    const float* out_proj_w = (const float*)d_in[7];
    const float* conv2_w    = (const float*)d_in[8];
    const float* conv2_b    = (const float*)d_in[9];
    const float* q_w        = (const float*)d_in[10];
    const float* q_b        = (const float*)d_in[11];
    const float* k_w        = (const float*)d_in[12];
    const float* k_b        = (const float*)d_in[13];
    const float* logit_scale= (const float*)d_in[14];

    float* base = nullptr;
    cudaGetSymbolAddress((void**)&base, g_buf);
    float* p_sm  = base + OFF_SM;
    float* p_b2  = base + OFF_B2;
    float* p_v1  = base + OFF_V1;
    float* p_qkv = base + OFF_QKV;
    float* p_ao  = base + OFF_AO;
    float* p_w67 = base + OFF_W67;
    float* p_wq  = base + OFF_WQ;
    float* p_bq  = base + OFF_BQ;
    float* p_ql  = base + OFF_QL;
    float* p_kl  = base + OFF_KL;
    float* p_rm  = base + OFF_RM;
    float* p_cm  = base + OFF_CM;
    float* p_S   = base + OFF_S;

    sent_mean_kernel<<<32, 512>>>(sentf, masks, p_sm);
    bias2_kernel<<<2048, 256>>>(conv1_w, conv1_b, p_sm, p_b2);

    // v1 = bef @ conv1_w[:, :512]^T + bias2[b]
    gemm128<2><<<dim3(4, 49), 256>>>(bef, conv1_w, p_v1, p_b2, 512, 512, 1024, 512);
    // qkv = v1 @ in_proj_w^T
    gemm128<0><<<dim3(12, 49), 256>>>(p_v1, in_proj_w, p_qkv, nullptr, 512, 512, 512, 1536);

    size_t attn_smem = (2 * 196 * 65 + 8 * 64) * sizeof(float);
    cudaFuncSetAttribute(attn_kernel, cudaFuncAttributeMaxDynamicSharedMemorySize, (int)attn_smem);
    attn_kernel<<<256, 256, attn_smem>>>(p_qkv, p_ao);

    // fused weights
    gemm64_nt<<<dim3(8, 8), 256>>>(conv2_w, out_proj_w, p_w67, 512, 512, 512, 512);
    gemm64_nt<<<dim3(8, 8), 256>>>(q_w, p_w67, p_wq, 512, 512, 512, 512);
    bq_kernel<<<1, 512>>>(q_w, conv2_b, q_b, p_bq);

    // QL = attn_o @ Wq^T + bq ; KL = aft @ k_w^T + k_b
    gemm128<1><<<dim3(4, 49), 256>>>(p_ao, p_wq, p_ql, p_bq, 512, 512, 512, 512);
    gemm128<1><<<dim3(4, 49), 256>>>(aft, k_w, p_kl, k_b, 512, 512, 512, 512);

    // pair logits + fused max reductions
    pair_kernel<<<dim3(2, 2, 1024), 256>>>(p_ql, p_kl, p_rm, p_cm);
    reduce_s_kernel<<<1024, 256>>>(p_rm, p_cm, logit_scale, p_S);
    loss_kernel<<<1, 1024>>>(p_S, (float*)d_out);
}

// round 4
// speedup vs baseline: 2.7023x; 1.7858x over previous
#include <cuda_runtime.h>
#include <cuda_bf16.h>
#include <math.h>
#include <stdint.h>

// Shapes fixed: B=32, LV=196, LT=40, D=512, H=8, DH=64, R=B*LV=6272 (=49*128)

// ---------------------------------------------------------------------------
// Scratch buffer (device global; no allocations)
// ---------------------------------------------------------------------------
#define OFF_SM   0u
#define OFF_B2   16384u
#define OFF_V1   32768u
#define OFF_QKV  3244032u
#define OFF_AO   12877824u
#define OFF_W67  16089088u
#define OFF_WQ   16351232u
#define OFF_BQ   16613376u
#define OFF_QL   16613888u
#define OFF_KL   19825152u
#define OFF_S    23036416u   // 1024 floats
#define OFF_QLH  23037440u   // bf16 6272*512 -> 1605632 float slots
#define OFF_QLL  24643072u
#define OFF_KLH  26248704u
#define OFF_KLL  27854336u
#define OFF_RPU  29459968u   // uint 32*6272 = 200704
#define OFF_CPU  29660672u
#define TOTAL_F  29861376u

__device__ __align__(256) float g_buf[TOTAL_F];

// ---------------------------------------------------------------------------
// mma.sync / ldmatrix helpers (sm_80+ path; assembles under compute_103)
// ---------------------------------------------------------------------------
__device__ __forceinline__ uint32_t smem_u32(const void* p) {
    uint32_t a;
    asm("{ .reg .u64 t; cvta.to.shared.u64 t, %1; cvt.u32.u64 %0, t; }" : "=r"(a) : "l"(p));
    return a;
}
__device__ __forceinline__ void ldsm_x4(uint32_t* r, uint32_t addr) {
    asm volatile("ldmatrix.sync.aligned.m8n8.x4.shared.b16 {%0,%1,%2,%3}, [%4];"
                 : "=r"(r[0]), "=r"(r[1]), "=r"(r[2]), "=r"(r[3]) : "r"(addr));
}
__device__ __forceinline__ void ldsm_x2(uint32_t* r, uint32_t addr) {
    asm volatile("ldmatrix.sync.aligned.m8n8.x2.shared.b16 {%0,%1}, [%2];"
                 : "=r"(r[0]), "=r"(r[1]) : "r"(addr));
}
__device__ __forceinline__ void mma_bf16(float* d, const uint32_t* a, const uint32_t* b) {
    asm volatile("mma.sync.aligned.m16n8k16.row.col.f32.bf16.bf16.f32 "
                 "{%0,%1,%2,%3}, {%4,%5,%6,%7}, {%8,%9}, {%0,%1,%2,%3};"
                 : "+f"(d[0]), "+f"(d[1]), "+f"(d[2]), "+f"(d[3])
                 : "r"(a[0]), "r"(a[1]), "r"(a[2]), "r"(a[3]), "r"(b[0]), "r"(b[1]));
}
#define SWZ128(off) ((off) ^ (((off) >> 3) & 0x70))

// ordered-uint encoding for float atomicMax
__device__ __forceinline__ unsigned enc_f(float f) {
    unsigned u = __float_as_uint(f);
    return u ^ ((((int)u >> 31)) | 0x80000000u);
}
__device__ __forceinline__ float dec_f(unsigned u) {
    unsigned m = (u & 0x80000000u) ? 0x80000000u : 0xFFFFFFFFu;
    return __uint_as_float(u ^ m);
}

// ---------------------------------------------------------------------------
__global__ void sent_mean_kernel(const float* __restrict__ sentf,
                                 const float* __restrict__ masks,
                                 float* __restrict__ sm) {
    int b = blockIdx.x, d = threadIdx.x;
    float s = 0.f;
    #pragma unroll
    for (int t = 0; t < 40; t++)
        s += sentf[(b * 40 + t) * 512 + d] * masks[b * 40 + t];
    sm[b * 512 + d] = s * (1.f / 40.f);
}

__global__ void bias2_kernel(const float* __restrict__ conv1_w,
                             const float* __restrict__ conv1_b,
                             const float* __restrict__ sm,
                             float* __restrict__ b2) {
    int gw = (blockIdx.x * blockDim.x + threadIdx.x) >> 5;
    int lane = threadIdx.x & 31;
    int b = gw >> 9, o = gw & 511;
    const float* wrow = conv1_w + o * 1024 + 512;
    const float* srow = sm + b * 512;
    float s = 0.f;
    for (int c = lane; c < 512; c += 32) s += wrow[c] * srow[c];
    #pragma unroll
    for (int off = 16; off; off >>= 1) s += __shfl_xor_sync(0xffffffffu, s, off);
    if (lane == 0) b2[b * 512 + o] = conv1_b[o] + s;
}

__global__ void bq_kernel(const float* __restrict__ q_w,
                          const float* __restrict__ conv2_b,
                          const float* __restrict__ q_b,
                          float* __restrict__ bq) {
    int q = threadIdx.x;
    float s = 0.f;
    for (int o = 0; o < 512; o++) s += q_w[q * 512 + o] * conv2_b[o];
    bq[q] = q_b[q] + s;
}

// ---------------------------------------------------------------------------
// Small fp32 GEMM for 512x512x512 weight fusions. C = A*B (both row-major).
// ---------------------------------------------------------------------------
__global__ void gemm64_nt(const float* __restrict__ A, const float* __restrict__ B,
                          float* __restrict__ C, int K, int lda, int ldb, int ldc) {
    __shared__ float As[32][65];
    __shared__ float Bs[32][65];
    int tid = threadIdx.x;
    int tx = tid & 15, ty = tid >> 4;
    int n0 = blockIdx.x * 64, m0 = blockIdx.y * 64;
    float acc[4][4] = {};
    for (int k0 = 0; k0 < K; k0 += 32) {
        #pragma unroll
        for (int i = 0; i < 8; i++) {
            int idx = tid + i * 256;
            int k = idx & 31, r = idx >> 5;
            As[k][r] = A[(m0 + r) * lda + k0 + k];
            int n = idx & 63, kk = idx >> 6;
            Bs[kk][n] = B[(k0 + kk) * ldb + n0 + n];
        }
        __syncthreads();
        #pragma unroll
        for (int k = 0; k < 32; k++) {
            float ar[4], br[4];
            #pragma unroll
            for (int i = 0; i < 4; i++) ar[i] = As[k][ty * 4 + i];
            #pragma unroll
            for (int j = 0; j < 4; j++) br[j] = Bs[k][tx * 4 + j];
            #pragma unroll
            for (int i = 0; i < 4; i++)
                #pragma unroll
                for (int j = 0; j < 4; j++) acc[i][j] += ar[i] * br[j];
        }
        __syncthreads();
    }
    #pragma unroll
    for (int i = 0; i < 4; i++)
        #pragma unroll
        for (int j = 0; j < 4; j++)
            C[(m0 + ty * 4 + i) * ldc + n0 + tx * 4 + j] = acc[i][j];
}

// ---------------------------------------------------------------------------
// fp32 SIMT GEMM: C = A(MxK) * B(NxK)^T, 128x128 tile, 8x8 micro, BK=8, dbuf.
// ---------------------------------------------------------------------------
template<int MODE>
__global__ void __launch_bounds__(256) gemm128(
        const float* __restrict__ A, const float* __restrict__ B,
        float* __restrict__ C, const float* __restrict__ bias,
        int K, int lda, int ldb, int ldc) {
    __shared__ float As[2][8][132];
    __shared__ float Bs[2][8][132];
    int tid = threadIdx.x;
    int tx = tid & 15, ty = tid >> 4;
    int row = tid >> 1, seg = tid & 1;
    int m0 = blockIdx.y * 128, n0 = blockIdx.x * 128;

    const float* Abase = A + (m0 + row) * lda + seg * 4;
    const float* Bbase = B + (n0 + row) * ldb + seg * 4;

    float acc[8][8] = {};
    float4 pa = *(const float4*)Abase;
    float4 pb = *(const float4*)Bbase;
    As[0][seg * 4 + 0][row] = pa.x; As[0][seg * 4 + 1][row] = pa.y;
    As[0][seg * 4 + 2][row] = pa.z; As[0][seg * 4 + 3][row] = pa.w;
    Bs[0][seg * 4 + 0][row] = pb.x; Bs[0][seg * 4 + 1][row] = pb.y;
    Bs[0][seg * 4 + 2][row] = pb.z; Bs[0][seg * 4 + 3][row] = pb.w;
    __syncthreads();

    int NK = K >> 3;
    for (int kt = 0; kt < NK; kt++) {
        int cur = kt & 1;
        if (kt + 1 < NK) {
            pa = *(const float4*)(Abase + (kt + 1) * 8);
            pb = *(const float4*)(Bbase + (kt + 1) * 8);
        }
        #pragma unroll
        for (int k = 0; k < 8; k++) {
            float ar[8], br[8];
            *(float4*)(ar)     = *(const float4*)&As[cur][k][ty * 4];
            *(float4*)(ar + 4) = *(const float4*)&As[cur][k][64 + ty * 4];
            *(float4*)(br)     = *(const float4*)&Bs[cur][k][tx * 4];
            *(float4*)(br + 4) = *(const float4*)&Bs[cur][k][64 + tx * 4];
            #pragma unroll
            for (int i = 0; i < 8; i++)
                #pragma unroll
                for (int j = 0; j < 8; j++)
                    acc[i][j] += ar[i] * br[j];
        }
        if (kt + 1 < NK) {
            int nxt = cur ^ 1;
            As[nxt][seg * 4 + 0][row] = pa.x; As[nxt][seg * 4 + 1][row] = pa.y;
            As[nxt][seg * 4 + 2][row] = pa.z; As[nxt][seg * 4 + 3][row] = pa.w;
            Bs[nxt][seg * 4 + 0][row] = pb.x; Bs[nxt][seg * 4 + 1][row] = pb.y;
            Bs[nxt][seg * 4 + 2][row] = pb.z; Bs[nxt][seg * 4 + 3][row] = pb.w;
        }
        __syncthreads();
    }

    #pragma unroll
    for (int i = 0; i < 8; i++) {
        int r = m0 + ty * 4 + (i & 3) + ((i >> 2) << 6);
        int boff = (MODE == 2) ? (r / 196) * 512 : 0;
        #pragma unroll
        for (int hj = 0; hj < 2; hj++) {
            int c = n0 + tx * 4 + (hj << 6);
            float4 v;
            v.x = acc[i][hj * 4 + 0]; v.y = acc[i][hj * 4 + 1];
            v.z = acc[i][hj * 4 + 2]; v.w = acc[i][hj * 4 + 3];
            if (MODE == 1) {
                v.x += bias[c]; v.y += bias[c + 1]; v.z += bias[c + 2]; v.w += bias[c + 3];
            }
            if (MODE == 2) {
                v.x += bias[boff + c]; v.y += bias[boff + c + 1];
                v.z += bias[boff + c + 2]; v.w += bias[boff + c + 3];
            }
            *(float4*)&C[r * ldc + c] = v;
        }
    }
}

// ---------------------------------------------------------------------------
// Attention: one CTA per (b,h).
// ---------------------------------------------------------------------------
__global__ void attn_kernel(const float* __restrict__ qkv, float* __restrict__ out) {
    int b = blockIdx.x >> 3, h = blockIdx.x & 7;
    extern __shared__ float smemf[];
    float* ks = smemf;
    float* vs = smemf + 196 * 65;
    float* qs = smemf + 2 * 196 * 65;
    int tid = threadIdx.x;
    const float* base = qkv + b * (196 * 1536) + h * 64;
    for (int idx = tid; idx < 196 * 64; idx += 256) {
        int m = idx >> 6, d = idx & 63;
        ks[m * 65 + d] = base[m * 1536 + 512 + d];
        vs[m * 65 + d] = base[m * 1536 + 1024 + d];
    }
    __syncthreads();
    int w = tid >> 5, lane = tid & 31;
    for (int l = w; l < 196; l += 8) {
        qs[w * 64 + lane]      = base[l * 1536 + lane];
        qs[w * 64 + lane + 32] = base[l * 1536 + lane + 32];
        __syncwarp();
        float s[7];
        #pragma unroll
        for (int j = 0; j < 7; j++) {
            int m = j * 32 + lane;
            if (m < 196) {
                float acc = 0.f;
                #pragma unroll
                for (int d = 0; d < 64; d++) acc += qs[w * 64 + d] * ks[m * 65 + d];
                s[j] = acc * 0.125f;
            } else s[j] = -INFINITY;
        }
        float mx = s[0];
        #pragma unroll
        for (int j = 1; j < 7; j++) mx = fmaxf(mx, s[j]);
        #pragma unroll
        for (int off = 16; off; off >>= 1) mx = fmaxf(mx, __shfl_xor_sync(0xffffffffu, mx, off));
        float sum = 0.f;
        #pragma unroll
        for (int j = 0; j < 7; j++) { s[j] = expf(s[j] - mx); sum += s[j]; }
        #pragma unroll
        for (int off = 16; off; off >>= 1) sum += __shfl_xor_sync(0xffffffffu, sum, off);
        float inv = 1.f / sum;
        float o0 = 0.f, o1 = 0.f;
        #pragma unroll
        for (int j = 0; j < 7; j++) {
            #pragma unroll
            for (int mm = 0; mm < 32; mm++) {
                int m = j * 32 + mm;
                if (m >= 196) break;
                float p = __shfl_sync(0xffffffffu, s[j], mm);
                o0 += p * vs[m * 65 + lane];
                o1 += p * vs[m * 65 + lane + 32];
            }
        }
        int r = b * 196 + l;
        out[r * 512 + h * 64 + lane]      = o0 * inv;
        out[r * 512 + h * 64 + lane + 32] = o1 * inv;
        __syncwarp();
    }
}

// ---------------------------------------------------------------------------
// bf16 split: hi = bf16(x), lo = bf16(x - hi)
// ---------------------------------------------------------------------------
__global__ void split_kernel(const float* __restrict__ src,
                             __nv_bfloat16* __restrict__ hi,
                             __nv_bfloat16* __restrict__ lo, int n) {
    for (int i = blockIdx.x * blockDim.x + threadIdx.x; i < n; i += gridDim.x * blockDim.x) {
        float x = src[i];
        __nv_bfloat16 h = __float2bfloat16(x);
        hi[i] = h;
        lo[i] = __float2bfloat16(x - __bfloat162float(h));
    }
}

__global__ void init_parts_kernel(unsigned* __restrict__ p, int n) {
    for (int i = blockIdx.x * blockDim.x + threadIdx.x; i < n; i += gridDim.x * blockDim.x)
        p[i] = 0x007FFFFFu;   // enc(-inf)
}

// ---------------------------------------------------------------------------
// Pair kernel via mma.sync bf16x3: full 6272x6272x512 GEMM, 128x128 CTA tiles,
// fused row/col max epilogue -> ordered-uint atomicMax partials.
// rowparts[b][r] = max over cols of batch b in row r   (t2v path)
// colparts[a][c] = max over rows of batch a in col c   (v2t path)
// smem: 4 staging tiles (128x64 bf16, XOR-swizzled) = 64KB, then reused
// as the fp32 C tile 128x130 = 66560B.
// ---------------------------------------------------------------------------
#define PK_SMEM 66560
#define SM_AH 0
#define SM_AL 16384
#define SM_BH 32768
#define SM_BL 49152

__global__ void __launch_bounds__(256) pair_mma_kernel(
        const __nv_bfloat16* __restrict__ QLh, const __nv_bfloat16* __restrict__ QLl,
        const __nv_bfloat16* __restrict__ KLh, const __nv_bfloat16* __restrict__ KLl,
        unsigned* __restrict__ rowparts, unsigned* __restrict__ colparts) {
    extern __shared__ char smem[];
    float (*Ct)[130] = (float(*)[130])smem;
    int tid = threadIdx.x;
    int wid = tid >> 5, lane = tid & 31;
    int m0 = blockIdx.y * 128, n0 = blockIdx.x * 128;
    int wm0 = (wid >> 2) * 64, wn0 = (wid & 3) * 32;

    // per-lane ldmatrix addressing (within-tile byte offsets)
    int a_row = wm0 + (lane & 15);            // + i*16
    int a_ch  = (lane >> 4);                  // + ks*2 ; xor (a_row & 7)
    int b_row = wn0 + (lane & 7);             // + j*8
    int b_ch  = ((lane >> 3) & 1);            // + ks*2 ; xor (b_row & 7)
    uint32_t smem_b = smem_u32(smem);

    float d[4][4][4];
    #pragma unroll
    for (int i = 0; i < 4; i++)
        #pragma unroll
        for (int j = 0; j < 4; j++)
            #pragma unroll
            for (int q = 0; q < 4; q++) d[i][j][q] = 0.f;

    for (int kc = 0; kc < 8; kc++) {
        __syncthreads();   // previous iter's ldmatrix reads done before restage
        #pragma unroll
        for (int t = 0; t < 4; t++) {
            int s2 = tid + t * 256;
            int row = s2 >> 3, sc = s2 & 7;
            uint32_t sw = SWZ128((uint32_t)(row * 128 + sc * 16));
            long ga = (long)(m0 + row) * 512 + kc * 64 + sc * 8;
            long gb = (long)(n0 + row) * 512 + kc * 64 + sc * 8;
            *(uint4*)(smem + SM_AH + sw) = *(const uint4*)(QLh + ga);
            *(uint4*)(smem + SM_AL + sw) = *(const uint4*)(QLl + ga);
            *(uint4*)(smem + SM_BH + sw) = *(const uint4*)(KLh + gb);
            *(uint4*)(smem + SM_BL + sw) = *(const uint4*)(KLl + gb);
        }
        __syncthreads();

        #pragma unroll
        for (int ks = 0; ks < 4; ks++) {
            int ach = (ks * 2 + a_ch) ^ (a_row & 7);
            int bch = (ks * 2 + b_ch) ^ (b_row & 7);
            uint32_t ah[4][4], bh[4][2], bl[4][2], al[4][4];
            #pragma unroll
            for (int i = 0; i < 4; i++)
                ldsm_x4(ah[i], smem_b + SM_AH + (a_row + i * 16) * 128 + ach * 16);
            #pragma unroll
            for (int j = 0; j < 4; j++)
                ldsm_x2(bh[j], smem_b + SM_BH + (b_row + j * 8) * 128 + bch * 16);
            #pragma unroll
            for (int i = 0; i < 4; i++)
                #pragma unroll
                for (int j = 0; j < 4; j++) mma_bf16(d[i][j], ah[i], bh[j]);
            #pragma unroll
            for (int j = 0; j < 4; j++)
                ldsm_x2(bl[j], smem_b + SM_BL + (b_row + j * 8) * 128 + bch * 16);
            #pragma unroll
            for (int i = 0; i < 4; i++)
                #pragma unroll
                for (int j = 0; j < 4; j++) mma_bf16(d[i][j], ah[i], bl[j]);
            #pragma unroll
            for (int i = 0; i < 4; i++)
                ldsm_x4(al[i], smem_b + SM_AL + (a_row + i * 16) * 128 + ach * 16);
            #pragma unroll
            for (int i = 0; i < 4; i++)
                #pragma unroll
                for (int j = 0; j < 4; j++) mma_bf16(d[i][j], al[i], bh[j]);
        }
    }
    __syncthreads();   // all mma/ldmatrix done; reuse smem as C tile

    // store fragments: thread lane holds rows wm0+i*16+l/4 (+8), cols wn0+j*8+2*(l%4)
    int fr = lane >> 2, fc = (lane & 3) * 2;
    #pragma unroll
    for (int i = 0; i < 4; i++) {
        #pragma unroll
        for (int j = 0; j < 4; j++) {
            int r = wm0 + i * 16 + fr, c = wn0 + j * 8 + fc;
            *(float2*)&Ct[r][c]     = make_float2(d[i][j][0], d[i][j][1]);
            *(float2*)&Ct[r + 8][c] = make_float2(d[i][j][2], d[i][j][3]);
        }
    }
    __syncthreads();

    if (tid < 128) {
        // row max for row tid over the 128 cols (split at batch boundary)
        int r = tid, gr = m0 + r;
        int b0 = n0 / 196;
        int bnd = (b0 + 1) * 196 - n0;
        if (bnd > 128) bnd = 128;
        float m1 = -INFINITY, m2 = -INFINITY;
        for (int c = 0; c < 128; c++) {
            float v = Ct[r][c];
            if (c < bnd) m1 = fmaxf(m1, v); else m2 = fmaxf(m2, v);
        }
        atomicMax(&rowparts[b0 * 6272 + gr], enc_f(m1));
        if (bnd < 128)
            atomicMax(&rowparts[(b0 + 1) * 6272 + gr], enc_f(m2));
    } else {
        // col max for col tid-128 over the 128 rows (split at batch boundary)
        int c = tid - 128, gc = n0 + c;
        int a0 = m0 / 196;
        int bnd = (a0 + 1) * 196 - m0;
        if (bnd > 128) bnd = 128;
        float m1 = -INFINITY, m2 = -INFINITY;
        for (int r = 0; r < 128; r++) {
            float v = Ct[r][c];
            if (r < bnd) m1 = fmaxf(m1, v); else m2 = fmaxf(m2, v);
        }
        atomicMax(&colparts[a0 * 6272 + gc], enc_f(m1));
        if (bnd < 128)
            atomicMax(&colparts[(a0 + 1) * 6272 + gc], enc_f(m2));
    }
}

// ---------------------------------------------------------------------------
__global__ void reduce_s_kernel(const unsigned* __restrict__ rowparts,
                                const unsigned* __restrict__ colparts,
                                const float* __restrict__ logit_scale,
                                float* __restrict__ S) {
    int pair = blockIdx.x, tid = threadIdx.x;
    int a = pair >> 5, b = pair & 31;
    float s = 0.f;
    for (int l = tid; l < 196; l += 256)
        s += dec_f(rowparts[b * 6272 + a * 196 + l]);
    for (int m = tid; m < 196; m += 256)
        s += dec_f(colparts[a * 6272 + b * 196 + m]);
    __shared__ float red[256];
    red[tid] = s;
    __syncthreads();
    for (int st = 128; st; st >>= 1) {
        if (tid < st) red[tid] += red[tid + st];
        __syncthreads();
    }
    if (tid == 0) S[pair] = 0.5f * red[0] * (1.f / 196.f) * expf(logit_scale[0]);
}

__global__ void loss_kernel(const float* __restrict__ S, float* __restrict__ out) {
    int tid = threadIdx.x;
    int w = tid >> 5, lane = tid & 31;
    float rv = S[w * 32 + lane];
    float cv = S[lane * 32 + w];
    float rm = rv, cm = cv;
    #pragma unroll
    for (int off = 16; off; off >>= 1) {
        rm = fmaxf(rm, __shfl_xor_sync(0xffffffffu, rm, off));
        cm = fmaxf(cm, __shfl_xor_sync(0xffffffffu, cm, off));
    }
    float re = expf(rv - rm), cex = expf(cv - cm);
    #pragma unroll
    for (int off = 16; off; off >>= 1) {
        re  += __shfl_xor_sync(0xffffffffu, re, off);
        cex += __shfl_xor_sync(0xffffffffu, cex, off);
    }
    __shared__ float acc[32];
    if (lane == 0) {
        float dg = S[w * 33];
        acc[w] = (dg - (rm + logf(re))) + (dg - (cm + logf(cex)));
    }
    __syncthreads();
    if (tid == 0) {
        float t = 0.f;
        for (int i = 0; i < 32; i++) t += acc[i];
        out[0] = -0.5f * t * (1.f / 32.f);
    }
}

// ---------------------------------------------------------------------------
extern "C" void kernel_launch(void* const* d_in, const int* in_sizes, int n_in,
                              void* d_out, int out_size) {
    const float* bef        = (const float*)d_in[0];
    const float* sentf      = (const float*)d_in[1];
    const float* aft        = (const float*)d_in[2];
    const float* masks      = (const float*)d_in[3];
    const float* conv1_w    = (const float*)d_in[4];
    const float* conv1_b    = (const float*)d_in[5];
    const float* in_proj_w  = (const float*)d_in[6];
    const float* out_proj_w = (const float*)d_in[7];
    const float* conv2_w    = (const float*)d_in[8];
    const float* conv2_b    = (const float*)d_in[9];
    const float* q_w        = (const float*)d_in[10];
    const float* q_b        = (const float*)d_in[11];
    const float* k_w        = (const float*)d_in[12];
    const float* k_b        = (const float*)d_in[13];
    const float* logit_scale= (const float*)d_in[14];

    float* base = nullptr;
    cudaGetSymbolAddress((void**)&base, g_buf);
    float* p_sm  = base + OFF_SM;
    float* p_b2  = base + OFF_B2;
    float* p_v1  = base + OFF_V1;
    float* p_qkv = base + OFF_QKV;
    float* p_ao  = base + OFF_AO;
    float* p_w67 = base + OFF_W67;
    float* p_wq  = base + OFF_WQ;
    float* p_bq  = base + OFF_BQ;
    float* p_ql  = base + OFF_QL;
    float* p_kl  = base + OFF_KL;
    float* p_S   = base + OFF_S;
    __nv_bfloat16* p_qlh = (__nv_bfloat16*)(base + OFF_QLH);
    __nv_bfloat16* p_qll = (__nv_bfloat16*)(base + OFF_QLL);
    __nv_bfloat16* p_klh = (__nv_bfloat16*)(base + OFF_KLH);
    __nv_bfloat16* p_kll = (__nv_bfloat16*)(base + OFF_KLL);
    unsigned* p_rp = (unsigned*)(base + OFF_RPU);
    unsigned* p_cp = (unsigned*)(base + OFF_CPU);

    sent_mean_kernel<<<32, 512>>>(sentf, masks, p_sm);
    bias2_kernel<<<2048, 256>>>(conv1_w, conv1_b, p_sm, p_b2);
    init_parts_kernel<<<256, 256>>>(p_rp, 2 * 200704);   // rp and cp contiguous

    // v1 = bef @ conv1_w[:, :512]^T + bias2[b]
    gemm128<2><<<dim3(4, 49), 256>>>(bef, conv1_w, p_v1, p_b2, 512, 512, 1024, 512);
    // qkv = v1 @ in_proj_w^T
    gemm128<0><<<dim3(12, 49), 256>>>(p_v1, in_proj_w, p_qkv, nullptr, 512, 512, 512, 1536);

    size_t attn_smem = (2 * 196 * 65 + 8 * 64) * sizeof(float);
    cudaFuncSetAttribute(attn_kernel, cudaFuncAttributeMaxDynamicSharedMemorySize, (int)attn_smem);
    attn_kernel<<<256, 256, attn_smem>>>(p_qkv, p_ao);

    // fused weights
    gemm64_nt<<<dim3(8, 8), 256>>>(conv2_w, out_proj_w, p_w67, 512, 512, 512, 512);
    gemm64_nt<<<dim3(8, 8), 256>>>(q_w, p_w67, p_wq, 512, 512, 512, 512);
    bq_kernel<<<1, 512>>>(q_w, conv2_b, q_b, p_bq);

    // QL = attn_o @ Wq^T + bq ; KL = aft @ k_w^T + k_b
    gemm128<1><<<dim3(4, 49), 256>>>(p_ao, p_wq, p_ql, p_bq, 512, 512, 512, 512);
    gemm128<1><<<dim3(4, 49), 256>>>(aft, k_w, p_kl, k_b, 512, 512, 512, 512);

    // bf16 hi/lo splits
    split_kernel<<<1024, 256>>>(p_ql, p_qlh, p_qll, 6272 * 512);
    split_kernel<<<1024, 256>>>(p_kl, p_klh, p_kll, 6272 * 512);

    // tensor-core pair GEMM + fused max epilogue
    cudaFuncSetAttribute(pair_mma_kernel, cudaFuncAttributeMaxDynamicSharedMemorySize, PK_SMEM);
    pair_mma_kernel<<<dim3(49, 49), 256, PK_SMEM>>>(p_qlh, p_qll, p_klh, p_kll, p_rp, p_cp);

    reduce_s_kernel<<<1024, 256>>>(p_rp, p_cp, logit_scale, p_S);
    loss_kernel<<<1, 1024>>>(p_S, (float*)d_out);
}

// round 7
// speedup vs baseline: 2.8191x; 1.0432x over previous
#include <cuda_runtime.h>
#include <cuda_bf16.h>
#include <math.h>
#include <stdint.h>

// Shapes fixed: B=32, LV=196, LT=40, D=512, H=8, DH=64, R=B*LV=6272 (=49*128)

// ---------------------------------------------------------------------------
// Scratch buffer layout (float slots)
// ---------------------------------------------------------------------------
#define OFF_SM    0u         // 16384
#define OFF_B2    16384u     // 16384
#define OFF_BQ    32768u     // 512
#define OFF_W67   33280u     // 262144
#define OFF_WQ    295424u    // 262144
#define OFF_S     557568u    // 1024
#define OFF_RP    558592u    // 200704 (uint)
#define OFF_CP    759296u    // 200704 (uint)
#define OFF_V1    960000u    // 3211264 fp32
#define OFF_QKV   4171264u   // 9633792 fp32
#define OFF_AOH   13805056u  // bf16 6272x512 = 1605632 float slots each
#define OFF_AOL   15410688u
#define OFF_AFTH  17016320u
#define OFF_AFTL  18621952u
#define OFF_QLH   20227584u
#define OFF_QLL   21833216u
#define OFF_KLH   23438848u
#define OFF_KLL   25044480u
#define OFF_WQH   26650112u  // 65536 each
#define OFF_WQL   26715648u
#define OFF_KWH   26781184u
#define OFF_KWL   26846720u
#define TOTAL_F   26912256u

__device__ __align__(256) float g_buf[TOTAL_F];

// ---------------------------------------------------------------------------
// mma.sync / ldmatrix helpers
// ---------------------------------------------------------------------------
__device__ __forceinline__ uint32_t smem_u32(const void* p) {
    uint32_t a;
    asm("{ .reg .u64 t; cvta.to.shared.u64 t, %1; cvt.u32.u64 %0, t; }" : "=r"(a) : "l"(p));
    return a;
}
__device__ __forceinline__ void ldsm_x4(uint32_t* r, uint32_t addr) {
    asm volatile("ldmatrix.sync.aligned.m8n8.x4.shared.b16 {%0,%1,%2,%3}, [%4];"
                 : "=r"(r[0]), "=r"(r[1]), "=r"(r[2]), "=r"(r[3]) : "r"(addr));
}
__device__ __forceinline__ void ldsm_x2(uint32_t* r, uint32_t addr) {
    asm volatile("ldmatrix.sync.aligned.m8n8.x2.shared.b16 {%0,%1}, [%2];"
                 : "=r"(r[0]), "=r"(r[1]) : "r"(addr));
}
__device__ __forceinline__ void mma_bf16(float* d, const uint32_t* a, const uint32_t* b) {
    asm volatile("mma.sync.aligned.m16n8k16.row.col.f32.bf16.bf16.f32 "
                 "{%0,%1,%2,%3}, {%4,%5,%6,%7}, {%8,%9}, {%0,%1,%2,%3};"
                 : "+f"(d[0]), "+f"(d[1]), "+f"(d[2]), "+f"(d[3])
                 : "r"(a[0]), "r"(a[1]), "r"(a[2]), "r"(a[3]), "r"(b[0]), "r"(b[1]));
}
#define SWZ128(off) ((off) ^ (((off) >> 3) & 0x70))

__device__ __forceinline__ unsigned enc_f(float f) {
    unsigned u = __float_as_uint(f);
    return u ^ ((((int)u >> 31)) | 0x80000000u);
}
__device__ __forceinline__ float dec_f(unsigned u) {
    unsigned m = (u & 0x80000000u) ? 0x80000000u : 0xFFFFFFFFu;
    return __uint_as_float(u ^ m);
}

// ---------------------------------------------------------------------------
__global__ void sent_mean_kernel(const float* __restrict__ sentf,
                                 const float* __restrict__ masks,
                                 float* __restrict__ sm) {
    int b = blockIdx.x, d = threadIdx.x;
    float s = 0.f;
    #pragma unroll
    for (int t = 0; t < 40; t++)
        s += sentf[(b * 40 + t) * 512 + d] * masks[b * 40 + t];
    sm[b * 512 + d] = s * (1.f / 40.f);
}

__global__ void bias2_kernel(const float* __restrict__ conv1_w,
                             const float* __restrict__ conv1_b,
                             const float* __restrict__ sm,
                             float* __restrict__ b2) {
    int gw = (blockIdx.x * blockDim.x + threadIdx.x) >> 5;
    int lane = threadIdx.x & 31;
    int b = gw >> 9, o = gw & 511;
    const float* wrow = conv1_w + o * 1024 + 512;
    const float* srow = sm + b * 512;
    float s = 0.f;
    for (int c = lane; c < 512; c += 32) s += wrow[c] * srow[c];
    #pragma unroll
    for (int off = 16; off; off >>= 1) s += __shfl_xor_sync(0xffffffffu, s, off);
    if (lane == 0) b2[b * 512 + o] = conv1_b[o] + s;
}

__global__ void bq_kernel(const float* __restrict__ q_w,
                          const float* __restrict__ conv2_b,
                          const float* __restrict__ q_b,
                          float* __restrict__ bq) {
    int q = threadIdx.x;
    float s = 0.f;
    for (int o = 0; o < 512; o++) s += q_w[q * 512 + o] * conv2_b[o];
    bq[q] = q_b[q] + s;
}

// ---------------------------------------------------------------------------
// Small fp32 GEMM for 512x512x512 weight fusions. C = A*B (both row-major).
// ---------------------------------------------------------------------------
__global__ void gemm64_nt(const float* __restrict__ A, const float* __restrict__ B,
                          float* __restrict__ C, int K, int lda, int ldb, int ldc) {
    __shared__ float As[32][65];
    __shared__ float Bs[32][65];
    int tid = threadIdx.x;
    int tx = tid & 15, ty = tid >> 4;
    int n0 = blockIdx.x * 64, m0 = blockIdx.y * 64;
    float acc[4][4] = {};
    for (int k0 = 0; k0 < K; k0 += 32) {
        #pragma unroll
        for (int i = 0; i < 8; i++) {
            int idx = tid + i * 256;
            int k = idx & 31, r = idx >> 5;
            As[k][r] = A[(m0 + r) * lda + k0 + k];
            int n = idx & 63, kk = idx >> 6;
            Bs[kk][n] = B[(k0 + kk) * ldb + n0 + n];
        }
        __syncthreads();
        #pragma unroll
        for (int k = 0; k < 32; k++) {
            float ar[4], br[4];
            #pragma unroll
            for (int i = 0; i < 4; i++) ar[i] = As[k][ty * 4 + i];
            #pragma unroll
            for (int j = 0; j < 4; j++) br[j] = Bs[k][tx * 4 + j];
            #pragma unroll
            for (int i = 0; i < 4; i++)
                #pragma unroll
                for (int j = 0; j < 4; j++) acc[i][j] += ar[i] * br[j];
        }
        __syncthreads();
    }
    #pragma unroll
    for (int i = 0; i < 4; i++)
        #pragma unroll
        for (int j = 0; j < 4; j++)
            C[(m0 + ty * 4 + i) * ldc + n0 + tx * 4 + j] = acc[i][j];
}

// ---------------------------------------------------------------------------
// fp32 SIMT GEMM: C = A(MxK) * B(NxK)^T, 128x128 tile, 8x8 micro, BK=8, dbuf.
// MODE 0: plain. MODE 2: +bias[(r/196)*512+n].
// ---------------------------------------------------------------------------
template<int MODE>
__global__ void __launch_bounds__(256) gemm128(
        const float* __restrict__ A, const float* __restrict__ B,
        float* __restrict__ C, const float* __restrict__ bias,
        int K, int lda, int ldb, int ldc) {
    __shared__ float As[2][8][132];
    __shared__ float Bs[2][8][132];
    int tid = threadIdx.x;
    int tx = tid & 15, ty = tid >> 4;
    int row = tid >> 1, seg = tid & 1;
    int m0 = blockIdx.y * 128, n0 = blockIdx.x * 128;

    const float* Abase = A + (m0 + row) * lda + seg * 4;
    const float* Bbase = B + (n0 + row) * ldb + seg * 4;

    float acc[8][8] = {};
    float4 pa = *(const float4*)Abase;
    float4 pb = *(const float4*)Bbase;
    As[0][seg * 4 + 0][row] = pa.x; As[0][seg * 4 + 1][row] = pa.y;
    As[0][seg * 4 + 2][row] = pa.z; As[0][seg * 4 + 3][row] = pa.w;
    Bs[0][seg * 4 + 0][row] = pb.x; Bs[0][seg * 4 + 1][row] = pb.y;
    Bs[0][seg * 4 + 2][row] = pb.z; Bs[0][seg * 4 + 3][row] = pb.w;
    __syncthreads();

    int NK = K >> 3;
    for (int kt = 0; kt < NK; kt++) {
        int cur = kt & 1;
        if (kt + 1 < NK) {
            pa = *(const float4*)(Abase + (kt + 1) * 8);
            pb = *(const float4*)(Bbase + (kt + 1) * 8);
        }
        #pragma unroll
        for (int k = 0; k < 8; k++) {
            float ar[8], br[8];
            *(float4*)(ar)     = *(const float4*)&As[cur][k][ty * 4];
            *(float4*)(ar + 4) = *(const float4*)&As[cur][k][64 + ty * 4];
            *(float4*)(br)     = *(const float4*)&Bs[cur][k][tx * 4];
            *(float4*)(br + 4) = *(const float4*)&Bs[cur][k][64 + tx * 4];
            #pragma unroll
            for (int i = 0; i < 8; i++)
                #pragma unroll
                for (int j = 0; j < 8; j++)
                    acc[i][j] += ar[i] * br[j];
        }
        if (kt + 1 < NK) {
            int nxt = cur ^ 1;
            As[nxt][seg * 4 + 0][row] = pa.x; As[nxt][seg * 4 + 1][row] = pa.y;
            As[nxt][seg * 4 + 2][row] = pa.z; As[nxt][seg * 4 + 3][row] = pa.w;
            Bs[nxt][seg * 4 + 0][row] = pb.x; Bs[nxt][seg * 4 + 1][row] = pb.y;
            Bs[nxt][seg * 4 + 2][row] = pb.z; Bs[nxt][seg * 4 + 3][row] = pb.w;
        }
        __syncthreads();
    }

    #pragma unroll
    for (int i = 0; i < 8; i++) {
        int r = m0 + ty * 4 + (i & 3) + ((i >> 2) << 6);
        int boff = (MODE == 2) ? (r / 196) * 512 : 0;
        #pragma unroll
        for (int hj = 0; hj < 2; hj++) {
            int c = n0 + tx * 4 + (hj << 6);
            float4 v;
            v.x = acc[i][hj * 4 + 0]; v.y = acc[i][hj * 4 + 1];
            v.z = acc[i][hj * 4 + 2]; v.w = acc[i][hj * 4 + 3];
            if (MODE == 2) {
                v.x += bias[boff + c]; v.y += bias[boff + c + 1];
                v.z += bias[boff + c + 2]; v.w += bias[boff + c + 3];
            }
            *(float4*)&C[r * ldc + c] = v;
        }
    }
}

// ---------------------------------------------------------------------------
// Splits: hi = bf16(x), lo = bf16(x - hi). Strided source.
// ---------------------------------------------------------------------------
__global__ void split_str_kernel(const float* __restrict__ src,
                                 __nv_bfloat16* __restrict__ hi,
                                 __nv_bfloat16* __restrict__ lo,
                                 int n, int stride) {
    for (int i = blockIdx.x * blockDim.x + threadIdx.x; i < n; i += gridDim.x * blockDim.x) {
        int row = i >> 9, col = i & 511;
        float x = src[row * stride + col];
        __nv_bfloat16 h = __float2bfloat16(x);
        hi[i] = h;
        lo[i] = __float2bfloat16(x - __bfloat162float(h));
    }
}

__global__ void init_parts_kernel(unsigned* __restrict__ p, int n) {
    for (int i = blockIdx.x * blockDim.x + threadIdx.x; i < n; i += gridDim.x * blockDim.x)
        p[i] = 0x007FFFFFu;   // enc(-inf)
}

// ---------------------------------------------------------------------------
// bf16x3 mma GEMM (MODE 1): C[M,N] = A(Mx512)@W(Nx512)^T + bias[n],
// output as bf16 hi/lo splits. 128x128 CTA tile, 8 warps x (64x32).
// ---------------------------------------------------------------------------
#define MG_SMEM 65536
#define SM_AH 0
#define SM_AL 16384
#define SM_BH 32768
#define SM_BL 49152

__global__ void __launch_bounds__(256) mma_gemm_b1(
        const __nv_bfloat16* __restrict__ Ah, const __nv_bfloat16* __restrict__ Al,
        const __nv_bfloat16* __restrict__ Wh, const __nv_bfloat16* __restrict__ Wl,
        __nv_bfloat16* __restrict__ outh, __nv_bfloat16* __restrict__ outl,
        const float* __restrict__ bias) {
    extern __shared__ char smem[];
    int tid = threadIdx.x;
    int wid = tid >> 5, lane = tid & 31;
    int m0 = blockIdx.y * 128, n0 = blockIdx.x * 128;
    int wm0 = (wid >> 2) * 64, wn0 = (wid & 3) * 32;

    int a_row = wm0 + (lane & 15);
    int a_ch  = (lane >> 4);
    int b_row = wn0 + (lane & 7);
    int b_ch  = ((lane >> 3) & 1);
    uint32_t smem_b = smem_u32(smem);

    float d[4][4][4];
    #pragma unroll
    for (int i = 0; i < 4; i++)
        #pragma unroll
        for (int j = 0; j < 4; j++)
            #pragma unroll
            for (int q = 0; q < 4; q++) d[i][j][q] = 0.f;

    for (int kc = 0; kc < 8; kc++) {
        __syncthreads();
        #pragma unroll
        for (int t = 0; t < 4; t++) {
            int s2 = tid + t * 256;
            int row = s2 >> 3, sc = s2 & 7;
            uint32_t sw = SWZ128((uint32_t)(row * 128 + sc * 16));
            long ga = (long)(m0 + row) * 512 + kc * 64 + sc * 8;
            long gb = (long)(n0 + row) * 512 + kc * 64 + sc * 8;
            *(uint4*)(smem + SM_AH + sw) = *(const uint4*)(Ah + ga);
            *(uint4*)(smem + SM_AL + sw) = *(const uint4*)(Al + ga);
            *(uint4*)(smem + SM_BH + sw) = *(const uint4*)(Wh + gb);
            *(uint4*)(smem + SM_BL + sw) = *(const uint4*)(Wl + gb);
        }
        __syncthreads();

        #pragma unroll
        for (int ks = 0; ks < 4; ks++) {
            int ach = (ks * 2 + a_ch) ^ (a_row & 7);
            int bch = (ks * 2 + b_ch) ^ (b_row & 7);
            uint32_t ah[4][4], bh[4][2], bl[4][2], al[4][4];
            #pragma unroll
            for (int i = 0; i < 4; i++)
                ldsm_x4(ah[i], smem_b + SM_AH + (a_row + i * 16) * 128 + ach * 16);
            #pragma unroll
            for (int j = 0; j < 4; j++)
                ldsm_x2(bh[j], smem_b + SM_BH + (b_row + j * 8) * 128 + bch * 16);
            #pragma unroll
            for (int i = 0; i < 4; i++)
                #pragma unroll
                for (int j = 0; j < 4; j++) mma_bf16(d[i][j], ah[i], bh[j]);
            #pragma unroll
            for (int j = 0; j < 4; j++)
                ldsm_x2(bl[j], smem_b + SM_BL + (b_row + j * 8) * 128 + bch * 16);
            #pragma unroll
            for (int i = 0; i < 4; i++)
                #pragma unroll
                for (int j = 0; j < 4; j++) mma_bf16(d[i][j], ah[i], bl[j]);
            #pragma unroll
            for (int i = 0; i < 4; i++)
                ldsm_x4(al[i], smem_b + SM_AL + (a_row + i * 16) * 128 + ach * 16);
            #pragma unroll
            for (int i = 0; i < 4; i++)
                #pragma unroll
                for (int j = 0; j < 4; j++) mma_bf16(d[i][j], al[i], bh[j]);
        }
    }

    int fr = lane >> 2, fc = (lane & 3) * 2;
    #pragma unroll
    for (int i = 0; i < 4; i++) {
        #pragma unroll
        for (int j = 0; j < 4; j++) {
            int gc = n0 + wn0 + j * 8 + fc;
            float b0 = bias[gc], b1 = bias[gc + 1];
            #pragma unroll
            for (int hh = 0; hh < 2; hh++) {
                int gr = m0 + wm0 + i * 16 + fr + hh * 8;
                float v0 = d[i][j][hh * 2 + 0] + b0;
                float v1 = d[i][j][hh * 2 + 1] + b1;
                __nv_bfloat162 hp, lp;
                hp.x = __float2bfloat16(v0);
                hp.y = __float2bfloat16(v1);
                lp.x = __float2bfloat16(v0 - __bfloat162float(hp.x));
                lp.y = __float2bfloat16(v1 - __bfloat162float(hp.y));
                *(uint32_t*)&outh[(long)gr * 512 + gc] = *(uint32_t*)&hp;
                *(uint32_t*)&outl[(long)gr * 512 + gc] = *(uint32_t*)&lp;
            }
        }
    }
}

// ---------------------------------------------------------------------------
// Attention: one CTA per (b,h). Emits bf16 hi/lo splits of the output.
// ---------------------------------------------------------------------------
__global__ void attn_kernel(const float* __restrict__ qkv,
                            __nv_bfloat16* __restrict__ outh,
                            __nv_bfloat16* __restrict__ outl) {
    int b = blockIdx.x >> 3, h = blockIdx.x & 7;
    extern __shared__ float smemf[];
    float* ks = smemf;
    float* vs = smemf + 196 * 65;
    float* qs = smemf + 2 * 196 * 65;
    int tid = threadIdx.x;
    const float* base = qkv + b * (196 * 1536) + h * 64;
    for (int idx = tid; idx < 196 * 64; idx += 256) {
        int m = idx >> 6, d = idx & 63;
        ks[m * 65 + d] = base[m * 1536 + 512 + d];
        vs[m * 65 + d] = base[m * 1536 + 1024 + d];
    }
    __syncthreads();
    int w = tid >> 5, lane = tid & 31;
    for (int l = w; l < 196; l += 8) {
        qs[w * 64 + lane]      = base[l * 1536 + lane];
        qs[w * 64 + lane + 32] = base[l * 1536 + lane + 32];
        __syncwarp();
        float s[7];
        #pragma unroll
        for (int j = 0; j < 7; j++) {
            int m = j * 32 + lane;
            if (m < 196) {
                float acc = 0.f;
                #pragma unroll
                for (int d = 0; d < 64; d++) acc += qs[w * 64 + d] * ks[m * 65 + d];
                s[j] = acc * 0.125f;
            } else s[j] = -INFINITY;
        }
        float mx = s[0];
        #pragma unroll
        for (int j = 1; j < 7; j++) mx = fmaxf(mx, s[j]);
        #pragma unroll
        for (int off = 16; off; off >>= 1) mx = fmaxf(mx, __shfl_xor_sync(0xffffffffu, mx, off));
        float sum = 0.f;
        #pragma unroll
        for (int j = 0; j < 7; j++) { s[j] = expf(s[j] - mx); sum += s[j]; }
        #pragma unroll
        for (int off = 16; off; off >>= 1) sum += __shfl_xor_sync(0xffffffffu, sum, off);
        float inv = 1.f / sum;
        float o0 = 0.f, o1 = 0.f;
        #pragma unroll
        for (int j = 0; j < 7; j++) {
            #pragma unroll
            for (int mm = 0; mm < 32; mm++) {
                int m = j * 32 + mm;
                if (m >= 196) break;
                float p = __shfl_sync(0xffffffffu, s[j], mm);
                o0 += p * vs[m * 65 + lane];
                o1 += p * vs[m * 65 + lane + 32];
            }
        }
        int r = b * 196 + l;
        o0 *= inv; o1 *= inv;
        long i0 = (long)r * 512 + h * 64 + lane;
        __nv_bfloat16 h0 = __float2bfloat16(o0);
        __nv_bfloat16 h1 = __float2bfloat16(o1);
        outh[i0]      = h0;
        outh[i0 + 32] = h1;
        outl[i0]      = __float2bfloat16(o0 - __bfloat162float(h0));
        outl[i0 + 32] = __float2bfloat16(o1 - __bfloat162float(h1));
        __syncwarp();
    }
}

// ---------------------------------------------------------------------------
// Pair kernel via mma.sync bf16x3 with fused row/col max epilogue.
// ---------------------------------------------------------------------------
#define PK_SMEM 66560

__global__ void __launch_bounds__(256) pair_mma_kernel(
        const __nv_bfloat16* __restrict__ QLh, const __nv_bfloat16* __restrict__ QLl,
        const __nv_bfloat16* __restrict__ KLh, const __nv_bfloat16* __restrict__ KLl,
        unsigned* __restrict__ rowparts, unsigned* __restrict__ colparts) {
    extern __shared__ char smem[];
    float (*Ct)[130] = (float(*)[130])smem;
    int tid = threadIdx.x;
    int wid = tid >> 5, lane = tid & 31;
    int m0 = blockIdx.y * 128, n0 = blockIdx.x * 128;
    int wm0 = (wid >> 2) * 64, wn0 = (wid & 3) * 32;

    int a_row = wm0 + (lane & 15);
    int a_ch  = (lane >> 4);
    int b_row = wn0 + (lane & 7);
    int b_ch  = ((lane >> 3) & 1);
    uint32_t smem_b = smem_u32(smem);

    float d[4][4][4];
    #pragma unroll
    for (int i = 0; i < 4; i++)
        #pragma unroll
        for (int j = 0; j < 4; j++)
            #pragma unroll
            for (int q = 0; q < 4; q++) d[i][j][q] = 0.f;

    for (int kc = 0; kc < 8; kc++) {
        __syncthreads();
        #pragma unroll
        for (int t = 0; t < 4; t++) {
            int s2 = tid + t * 256;
            int row = s2 >> 3, sc = s2 & 7;
            uint32_t sw = SWZ128((uint32_t)(row * 128 + sc * 16));
            long ga = (long)(m0 + row) * 512 + kc * 64 + sc * 8;
            long gb = (long)(n0 + row) * 512 + kc * 64 + sc * 8;
            *(uint4*)(smem + SM_AH + sw) = *(const uint4*)(QLh + ga);
            *(uint4*)(smem + SM_AL + sw) = *(const uint4*)(QLl + ga);
            *(uint4*)(smem + SM_BH + sw) = *(const uint4*)(KLh + gb);
            *(uint4*)(smem + SM_BL + sw) = *(const uint4*)(KLl + gb);
        }
        __syncthreads();

        #pragma unroll
        for (int ks = 0; ks < 4; ks++) {
            int ach = (ks * 2 + a_ch) ^ (a_row & 7);
            int bch = (ks * 2 + b_ch) ^ (b_row & 7);
            uint32_t ah[4][4], bh[4][2], bl[4][2], al[4][4];
            #pragma unroll
            for (int i = 0; i < 4; i++)
                ldsm_x4(ah[i], smem_b + SM_AH + (a_row + i * 16) * 128 + ach * 16);
            #pragma unroll
            for (int j = 0; j < 4; j++)
                ldsm_x2(bh[j], smem_b + SM_BH + (b_row + j * 8) * 128 + bch * 16);
            #pragma unroll
            for (int i = 0; i < 4; i++)
                #pragma unroll
                for (int j = 0; j < 4; j++) mma_bf16(d[i][j], ah[i], bh[j]);
            #pragma unroll
            for (int j = 0; j < 4; j++)
                ldsm_x2(bl[j], smem_b + SM_BL + (b_row + j * 8) * 128 + bch * 16);
            #pragma unroll
            for (int i = 0; i < 4; i++)
                #pragma unroll
                for (int j = 0; j < 4; j++) mma_bf16(d[i][j], ah[i], bl[j]);
            #pragma unroll
            for (int i = 0; i < 4; i++)
                ldsm_x4(al[i], smem_b + SM_AL + (a_row + i * 16) * 128 + ach * 16);
            #pragma unroll
            for (int i = 0; i < 4; i++)
                #pragma unroll
                for (int j = 0; j < 4; j++) mma_bf16(d[i][j], al[i], bh[j]);
        }
    }
    __syncthreads();

    int fr = lane >> 2, fc = (lane & 3) * 2;
    #pragma unroll
    for (int i = 0; i < 4; i++) {
        #pragma unroll
        for (int j = 0; j < 4; j++) {
            int r = wm0 + i * 16 + fr, c = wn0 + j * 8 + fc;
            *(float2*)&Ct[r][c]     = make_float2(d[i][j][0], d[i][j][1]);
            *(float2*)&Ct[r + 8][c] = make_float2(d[i][j][2], d[i][j][3]);
        }
    }
    __syncthreads();

    if (tid < 128) {
        int r = tid, gr = m0 + r;
        int b0 = n0 / 196;
        int bnd = (b0 + 1) * 196 - n0;
        if (bnd > 128) bnd = 128;
        float m1 = -INFINITY, m2 = -INFINITY;
        for (int c = 0; c < 128; c++) {
            float v = Ct[r][c];
            if (c < bnd) m1 = fmaxf(m1, v); else m2 = fmaxf(m2, v);
        }
        atomicMax(&rowparts[b0 * 6272 + gr], enc_f(m1));
        if (bnd < 128)
            atomicMax(&rowparts[(b0 + 1) * 6272 + gr], enc_f(m2));
    } else {
        int c = tid - 128, gc = n0 + c;
        int a0 = m0 / 196;
        int bnd = (a0 + 1) * 196 - m0;
        if (bnd > 128) bnd = 128;
        float m1 = -INFINITY, m2 = -INFINITY;
        for (int r = 0; r < 128; r++) {
            float v = Ct[r][c];
            if (r < bnd) m1 = fmaxf(m1, v); else m2 = fmaxf(m2, v);
        }
        atomicMax(&colparts[a0 * 6272 + gc], enc_f(m1));
        if (bnd < 128)
            atomicMax(&colparts[(a0 + 1) * 6272 + gc], enc_f(m2));
    }
}

// ---------------------------------------------------------------------------
__global__ void reduce_s_kernel(const unsigned* __restrict__ rowparts,
                                const unsigned* __restrict__ colparts,
                                const float* __restrict__ logit_scale,
                                float* __restrict__ S) {
    int pair = blockIdx.x, tid = threadIdx.x;
    int a = pair >> 5, b = pair & 31;
    float s = 0.f;
    for (int l = tid; l < 196; l += 256)
        s += dec_f(rowparts[b * 6272 + a * 196 + l]);
    for (int m = tid; m < 196; m += 256)
        s += dec_f(colparts[a * 6272 + b * 196 + m]);
    __shared__ float red[256];
    red[tid] = s;
    __syncthreads();
    for (int st = 128; st; st >>= 1) {
        if (tid < st) red[tid] += red[tid + st];
        __syncthreads();
    }
    if (tid == 0) S[pair] = 0.5f * red[0] * (1.f / 196.f) * expf(logit_scale[0]);
}

__global__ void loss_kernel(const float* __restrict__ S, float* __restrict__ out) {
    int tid = threadIdx.x;
    int w = tid >> 5, lane = tid & 31;
    float rv = S[w * 32 + lane];
    float cv = S[lane * 32 + w];
    float rm = rv, cm = cv;
    #pragma unroll
    for (int off = 16; off; off >>= 1) {
        rm = fmaxf(rm, __shfl_xor_sync(0xffffffffu, rm, off));
        cm = fmaxf(cm, __shfl_xor_sync(0xffffffffu, cm, off));
    }
    float re = expf(rv - rm), cex = expf(cv - cm);
    #pragma unroll
    for (int off = 16; off; off >>= 1) {
        re  += __shfl_xor_sync(0xffffffffu, re, off);
        cex += __shfl_xor_sync(0xffffffffu, cex, off);
    }
    __shared__ float acc[32];
    if (lane == 0) {
        float dg = S[w * 33];
        acc[w] = (dg - (rm + logf(re))) + (dg - (cm + logf(cex)));
    }
    __syncthreads();
    if (tid == 0) {
        float t = 0.f;
        for (int i = 0; i < 32; i++) t += acc[i];
        out[0] = -0.5f * t * (1.f / 32.f);
    }
}

// ---------------------------------------------------------------------------
extern "C" void kernel_launch(void* const* d_in, const int* in_sizes, int n_in,
                              void* d_out, int out_size) {
    const float* bef        = (const float*)d_in[0];
    const float* sentf      = (const float*)d_in[1];
    const float* aft        = (const float*)d_in[2];
    const float* masks      = (const float*)d_in[3];
    const float* conv1_w    = (const float*)d_in[4];
    const float* conv1_b    = (const float*)d_in[5];
    const float* in_proj_w  = (const float*)d_in[6];
    const float* out_proj_w = (const float*)d_in[7];
    const float* conv2_w    = (const float*)d_in[8];
    const float* conv2_b    = (const float*)d_in[9];
    const float* q_w        = (const float*)d_in[10];
    const float* q_b        = (const float*)d_in[11];
    const float* k_w        = (const float*)d_in[12];
    const float* k_b        = (const float*)d_in[13];
    const float* logit_scale= (const float*)d_in[14];

    float* base = nullptr;
    cudaGetSymbolAddress((void**)&base, g_buf);
    float* p_sm  = base + OFF_SM;
    float* p_b2  = base + OFF_B2;
    float* p_bq  = base + OFF_BQ;
    float* p_w67 = base + OFF_W67;
    float* p_wq  = base + OFF_WQ;
    float* p_S   = base + OFF_S;
    float* p_v1  = base + OFF_V1;
    float* p_qkv = base + OFF_QKV;
    unsigned* p_rp = (unsigned*)(base + OFF_RP);
    unsigned* p_cp = (unsigned*)(base + OFF_CP);
    #define BF16P(off) ((__nv_bfloat16*)(base + (off)))
    __nv_bfloat16* aoh  = BF16P(OFF_AOH);  __nv_bfloat16* aol  = BF16P(OFF_AOL);
    __nv_bfloat16* afth = BF16P(OFF_AFTH); __nv_bfloat16* aftl = BF16P(OFF_AFTL);
    __nv_bfloat16* qlh  = BF16P(OFF_QLH);  __nv_bfloat16* qll  = BF16P(OFF_QLL);
    __nv_bfloat16* klh  = BF16P(OFF_KLH);  __nv_bfloat16* kll  = BF16P(OFF_KLL);
    __nv_bfloat16* wqh  = BF16P(OFF_WQH);  __nv_bfloat16* wql  = BF16P(OFF_WQL);
    __nv_bfloat16* kwh  = BF16P(OFF_KWH);  __nv_bfloat16* kwl  = BF16P(OFF_KWL);

    cudaFuncSetAttribute(mma_gemm_b1, cudaFuncAttributeMaxDynamicSharedMemorySize, MG_SMEM);
    cudaFuncSetAttribute(pair_mma_kernel, cudaFuncAttributeMaxDynamicSharedMemorySize, PK_SMEM);

    // prep: text mean, per-batch conv1 bias, init partials, aft/k_w splits
    sent_mean_kernel<<<32, 512>>>(sentf, masks, p_sm);
    bias2_kernel<<<2048, 256>>>(conv1_w, conv1_b, p_sm, p_b2);
    init_parts_kernel<<<256, 256>>>(p_rp, 2 * 200704);
    split_str_kernel<<<1024, 256>>>(aft, afth, aftl, 6272 * 512, 512);
    split_str_kernel<<<256, 256>>>(k_w, kwh, kwl, 512 * 512, 512);

    // v1 = bef @ conv1_w[:, :512]^T + bias2[b]   (exact fp32)
    gemm128<2><<<dim3(4, 49), 256>>>(bef, conv1_w, p_v1, p_b2, 512, 512, 1024, 512);
    // qkv = v1 @ in_proj_w^T                     (exact fp32)
    gemm128<0><<<dim3(12, 49), 256>>>(p_v1, in_proj_w, p_qkv, nullptr, 512, 512, 512, 1536);

    size_t attn_smem = (2 * 196 * 65 + 8 * 64) * sizeof(float);
    cudaFuncSetAttribute(attn_kernel, cudaFuncAttributeMaxDynamicSharedMemorySize, (int)attn_smem);
    attn_kernel<<<256, 256, attn_smem>>>(p_qkv, aoh, aol);

    // fused weights: Wq = q_w @ conv2_w @ out_proj_w ; bq = q_b + q_w@conv2_b
    gemm64_nt<<<dim3(8, 8), 256>>>(conv2_w, out_proj_w, p_w67, 512, 512, 512, 512);
    gemm64_nt<<<dim3(8, 8), 256>>>(q_w, p_w67, p_wq, 512, 512, 512, 512);
    bq_kernel<<<1, 512>>>(q_w, conv2_b, q_b, p_bq);
    split_str_kernel<<<256, 256>>>(p_wq, wqh, wql, 512 * 512, 512);

    // QL = ao @ Wq^T + bq ; KL = aft @ k_w^T + k_b   (bf16x3 mma, split out)
    mma_gemm_b1<<<dim3(4, 49), 256, MG_SMEM>>>(aoh, aol, wqh, wql, qlh, qll, p_bq);
    mma_gemm_b1<<<dim3(4, 49), 256, MG_SMEM>>>(afth, aftl, kwh, kwl, klh, kll, k_b);

    // pair GEMM + fused max epilogue
    pair_mma_kernel<<<dim3(49, 49), 256, PK_SMEM>>>(qlh, qll, klh, kll, p_rp, p_cp);

    reduce_s_kernel<<<1024, 256>>>(p_rp, p_cp, logit_scale, p_S);
    loss_kernel<<<1, 1024>>>(p_S, (float*)d_out);
}

// round 9
// speedup vs baseline: 3.2296x; 1.1456x over previous
#include <cuda_runtime.h>
#include <cuda_fp16.h>
#include <cuda_bf16.h>
#include <math.h>
#include <stdint.h>

// Shapes fixed: B=32, LV=196, LT=40, D=512, H=8, DH=64, R=B*LV=6272 (=49*128)

// ---------------------------------------------------------------------------
// Scratch buffer layout (float slots) — identical to round 7
// ---------------------------------------------------------------------------
#define OFF_SM    0u
#define OFF_B2    16384u
#define OFF_BQ    32768u
#define OFF_W67   33280u
#define OFF_WQ    295424u
#define OFF_S     557568u
#define OFF_RP    558592u
#define OFF_CP    759296u
#define OFF_V1    960000u
#define OFF_QKV   4171264u
#define OFF_AOH   13805056u
#define OFF_AOL   15410688u
#define OFF_AFTH  17016320u
#define OFF_AFTL  18621952u
#define OFF_QLH   20227584u
#define OFF_QLL   21833216u
#define OFF_KLH   23438848u
#define OFF_KLL   25044480u
#define OFF_WQH   26650112u
#define OFF_WQL   26715648u
#define OFF_KWH   26781184u
#define OFF_KWL   26846720u
#define TOTAL_F   26912256u

__device__ __align__(256) float g_buf[TOTAL_F];

// ---------------------------------------------------------------------------
// mma.sync / ldmatrix / cp.async helpers
// ---------------------------------------------------------------------------
__device__ __forceinline__ uint32_t smem_u32(const void* p) {
    uint32_t a;
    asm("{ .reg .u64 t; cvta.to.shared.u64 t, %1; cvt.u32.u64 %0, t; }" : "=r"(a) : "l"(p));
    return a;
}
__device__ __forceinline__ void ldsm_x4(uint32_t* r, uint32_t addr) {
    asm volatile("ldmatrix.sync.aligned.m8n8.x4.shared.b16 {%0,%1,%2,%3}, [%4];"
                 : "=r"(r[0]), "=r"(r[1]), "=r"(r[2]), "=r"(r[3]) : "r"(addr));
}
__device__ __forceinline__ void ldsm_x2(uint32_t* r, uint32_t addr) {
    asm volatile("ldmatrix.sync.aligned.m8n8.x2.shared.b16 {%0,%1}, [%2];"
                 : "=r"(r[0]), "=r"(r[1]) : "r"(addr));
}
__device__ __forceinline__ void mma_bf16(float* d, const uint32_t* a, const uint32_t* b) {
    asm volatile("mma.sync.aligned.m16n8k16.row.col.f32.bf16.bf16.f32 "
                 "{%0,%1,%2,%3}, {%4,%5,%6,%7}, {%8,%9}, {%0,%1,%2,%3};"
                 : "+f"(d[0]), "+f"(d[1]), "+f"(d[2]), "+f"(d[3])
                 : "r"(a[0]), "r"(a[1]), "r"(a[2]), "r"(a[3]), "r"(b[0]), "r"(b[1]));
}
__device__ __forceinline__ void cp_async16(uint32_t dst, const void* src) {
    asm volatile("cp.async.cg.shared.global [%0], [%1], 16;" :: "r"(dst), "l"(src) : "memory");
}
__device__ __forceinline__ void cp_commit() {
    asm volatile("cp.async.commit_group;" ::: "memory");
}
template<int N>
__device__ __forceinline__ void cp_wait() {
    asm volatile("cp.async.wait_group %0;" :: "n"(N) : "memory");
}
#define SWZ128(off) ((off) ^ (((off) >> 3) & 0x70))

__device__ __forceinline__ unsigned enc_f(float f) {
    unsigned u = __float_as_uint(f);
    return u ^ ((((int)u >> 31)) | 0x80000000u);
}
__device__ __forceinline__ float dec_f(unsigned u) {
    unsigned m = (u & 0x80000000u) ? 0x80000000u : 0xFFFFFFFFu;
    return __uint_as_float(u ^ m);
}

// ---------------------------------------------------------------------------
__global__ void sent_mean_kernel(const float* __restrict__ sentf,
                                 const float* __restrict__ masks,
                                 float* __restrict__ sm) {
    int b = blockIdx.x, d = threadIdx.x;
    float s = 0.f;
    #pragma unroll
    for (int t = 0; t < 40; t++)
        s += sentf[(b * 40 + t) * 512 + d] * masks[b * 40 + t];
    sm[b * 512 + d] = s * (1.f / 40.f);
}

__global__ void bias2_kernel(const float* __restrict__ conv1_w,
                             const float* __restrict__ conv1_b,
                             const float* __restrict__ sm,
                             float* __restrict__ b2) {
    int gw = (blockIdx.x * blockDim.x + threadIdx.x) >> 5;
    int lane = threadIdx.x & 31;
    int b = gw >> 9, o = gw & 511;
    const float* wrow = conv1_w + o * 1024 + 512;
    const float* srow = sm + b * 512;
    float s = 0.f;
    for (int c = lane; c < 512; c += 32) s += wrow[c] * srow[c];
    #pragma unroll
    for (int off = 16; off; off >>= 1) s += __shfl_xor_sync(0xffffffffu, s, off);
    if (lane == 0) b2[b * 512 + o] = conv1_b[o] + s;
}

__global__ void bq_kernel(const float* __restrict__ q_w,
                          const float* __restrict__ conv2_b,
                          const float* __restrict__ q_b,
                          float* __restrict__ bq) {
    int q = threadIdx.x;
    float s = 0.f;
    for (int o = 0; o < 512; o++) s += q_w[q * 512 + o] * conv2_b[o];
    bq[q] = q_b[q] + s;
}

// ---------------------------------------------------------------------------
// Small fp32 GEMM for 512x512x512 weight fusions. C = A*B (both row-major).
// ---------------------------------------------------------------------------
__global__ void gemm64_nt(const float* __restrict__ A, const float* __restrict__ B,
                          float* __restrict__ C, int K, int lda, int ldb, int ldc) {
    __shared__ float As[32][65];
    __shared__ float Bs[32][65];
    int tid = threadIdx.x;
    int tx = tid & 15, ty = tid >> 4;
    int n0 = blockIdx.x * 64, m0 = blockIdx.y * 64;
    float acc[4][4] = {};
    for (int k0 = 0; k0 < K; k0 += 32) {
        #pragma unroll
        for (int i = 0; i < 8; i++) {
            int idx = tid + i * 256;
            int k = idx & 31, r = idx >> 5;
            As[k][r] = A[(m0 + r) * lda + k0 + k];
            int n = idx & 63, kk = idx >> 6;
            Bs[kk][n] = B[(k0 + kk) * ldb + n0 + n];
        }
        __syncthreads();
        #pragma unroll
        for (int k = 0; k < 32; k++) {
            float ar[4], br[4];
            #pragma unroll
            for (int i = 0; i < 4; i++) ar[i] = As[k][ty * 4 + i];
            #pragma unroll
            for (int j = 0; j < 4; j++) br[j] = Bs[k][tx * 4 + j];
            #pragma unroll
            for (int i = 0; i < 4; i++)
                #pragma unroll
                for (int j = 0; j < 4; j++) acc[i][j] += ar[i] * br[j];
        }
        __syncthreads();
    }
    #pragma unroll
    for (int i = 0; i < 4; i++)
        #pragma unroll
        for (int j = 0; j < 4; j++)
            C[(m0 + ty * 4 + i) * ldc + n0 + tx * 4 + j] = acc[i][j];
}

// ---------------------------------------------------------------------------
// fp32 SIMT GEMM: C = A(MxK) * B(NxK)^T, 128x128 tile, 8x8 micro, BK=8, dbuf.
// MODE 0: plain. MODE 2: +bias[(r/196)*512+n].
// ---------------------------------------------------------------------------
template<int MODE>
__global__ void __launch_bounds__(256) gemm128(
        const float* __restrict__ A, const float* __restrict__ B,
        float* __restrict__ C, const float* __restrict__ bias,
        int K, int lda, int ldb, int ldc) {
    __shared__ float As[2][8][132];
    __shared__ float Bs[2][8][132];
    int tid = threadIdx.x;
    int tx = tid & 15, ty = tid >> 4;
    int row = tid >> 1, seg = tid & 1;
    int m0 = blockIdx.y * 128, n0 = blockIdx.x * 128;

    const float* Abase = A + (m0 + row) * lda + seg * 4;
    const float* Bbase = B + (n0 + row) * ldb + seg * 4;

    float acc[8][8] = {};
    float4 pa = *(const float4*)Abase;
    float4 pb = *(const float4*)Bbase;
    As[0][seg * 4 + 0][row] = pa.x; As[0][seg * 4 + 1][row] = pa.y;
    As[0][seg * 4 + 2][row] = pa.z; As[0][seg * 4 + 3][row] = pa.w;
    Bs[0][seg * 4 + 0][row] = pb.x; Bs[0][seg * 4 + 1][row] = pb.y;
    Bs[0][seg * 4 + 2][row] = pb.z; Bs[0][seg * 4 + 3][row] = pb.w;
    __syncthreads();

    int NK = K >> 3;
    for (int kt = 0; kt < NK; kt++) {
        int cur = kt & 1;
        if (kt + 1 < NK) {
            pa = *(const float4*)(Abase + (kt + 1) * 8);
            pb = *(const float4*)(Bbase + (kt + 1) * 8);
        }
        #pragma unroll
        for (int k = 0; k < 8; k++) {
            float ar[8], br[8];
            *(float4*)(ar)     = *(const float4*)&As[cur][k][ty * 4];
            *(float4*)(ar + 4) = *(const float4*)&As[cur][k][64 + ty * 4];
            *(float4*)(br)     = *(const float4*)&Bs[cur][k][tx * 4];
            *(float4*)(br + 4) = *(const float4*)&Bs[cur][k][64 + tx * 4];
            #pragma unroll
            for (int i = 0; i < 8; i++)
                #pragma unroll
                for (int j = 0; j < 8; j++)
                    acc[i][j] += ar[i] * br[j];
        }
        if (kt + 1 < NK) {
            int nxt = cur ^ 1;
            As[nxt][seg * 4 + 0][row] = pa.x; As[nxt][seg * 4 + 1][row] = pa.y;
            As[nxt][seg * 4 + 2][row] = pa.z; As[nxt][seg * 4 + 3][row] = pa.w;
            Bs[nxt][seg * 4 + 0][row] = pb.x; Bs[nxt][seg * 4 + 1][row] = pb.y;
            Bs[nxt][seg * 4 + 2][row] = pb.z; Bs[nxt][seg * 4 + 3][row] = pb.w;
        }
        __syncthreads();
    }

    #pragma unroll
    for (int i = 0; i < 8; i++) {
        int r = m0 + ty * 4 + (i & 3) + ((i >> 2) << 6);
        int boff = (MODE == 2) ? (r / 196) * 512 : 0;
        #pragma unroll
        for (int hj = 0; hj < 2; hj++) {
            int c = n0 + tx * 4 + (hj << 6);
            float4 v;
            v.x = acc[i][hj * 4 + 0]; v.y = acc[i][hj * 4 + 1];
            v.z = acc[i][hj * 4 + 2]; v.w = acc[i][hj * 4 + 3];
            if (MODE == 2) {
                v.x += bias[boff + c]; v.y += bias[boff + c + 1];
                v.z += bias[boff + c + 2]; v.w += bias[boff + c + 3];
            }
            *(float4*)&C[r * ldc + c] = v;
        }
    }
}

// ---------------------------------------------------------------------------
// Splits: hi = bf16(x), lo = bf16(x - hi). Strided source.
// ---------------------------------------------------------------------------
__global__ void split_str_kernel(const float* __restrict__ src,
                                 __nv_bfloat16* __restrict__ hi,
                                 __nv_bfloat16* __restrict__ lo,
                                 int n, int stride) {
    for (int i = blockIdx.x * blockDim.x + threadIdx.x; i < n; i += gridDim.x * blockDim.x) {
        int row = i >> 9, col = i & 511;
        float x = src[row * stride + col];
        __nv_bfloat16 h = __float2bfloat16(x);
        hi[i] = h;
        lo[i] = __float2bfloat16(x - __bfloat162float(h));
    }
}

__global__ void init_parts_kernel(unsigned* __restrict__ p, int n) {
    for (int i = blockIdx.x * blockDim.x + threadIdx.x; i < n; i += gridDim.x * blockDim.x)
        p[i] = 0x007FFFFFu;   // enc(-inf)
}

// ---------------------------------------------------------------------------
// bf16x3 mma GEMM (MODE 1): C[M,N] = A(Mx512)@W(Nx512)^T + bias[n],
// output as bf16 hi/lo splits. 128x128 CTA tile, 8 warps x (64x32).
// (identical to round 7 — numerics preserved)
// ---------------------------------------------------------------------------
#define MG_SMEM 65536
#define SM_AH 0
#define SM_AL 16384
#define SM_BH 32768
#define SM_BL 49152

__global__ void __launch_bounds__(256) mma_gemm_b1(
        const __nv_bfloat16* __restrict__ Ah, const __nv_bfloat16* __restrict__ Al,
        const __nv_bfloat16* __restrict__ Wh, const __nv_bfloat16* __restrict__ Wl,
        __nv_bfloat16* __restrict__ outh, __nv_bfloat16* __restrict__ outl,
        const float* __restrict__ bias) {
    extern __shared__ char smem[];
    int tid = threadIdx.x;
    int wid = tid >> 5, lane = tid & 31;
    int m0 = blockIdx.y * 128, n0 = blockIdx.x * 128;
    int wm0 = (wid >> 2) * 64, wn0 = (wid & 3) * 32;

    int a_row = wm0 + (lane & 15);
    int a_ch  = (lane >> 4);
    int b_row = wn0 + (lane & 7);
    int b_ch  = ((lane >> 3) & 1);
    uint32_t smem_b = smem_u32(smem);

    float d[4][4][4];
    #pragma unroll
    for (int i = 0; i < 4; i++)
        #pragma unroll
        for (int j = 0; j < 4; j++)
            #pragma unroll
            for (int q = 0; q < 4; q++) d[i][j][q] = 0.f;

    for (int kc = 0; kc < 8; kc++) {
        __syncthreads();
        #pragma unroll
        for (int t = 0; t < 4; t++) {
            int s2 = tid + t * 256;
            int row = s2 >> 3, sc = s2 & 7;
            uint32_t sw = SWZ128((uint32_t)(row * 128 + sc * 16));
            long ga = (long)(m0 + row) * 512 + kc * 64 + sc * 8;
            long gb = (long)(n0 + row) * 512 + kc * 64 + sc * 8;
            *(uint4*)(smem + SM_AH + sw) = *(const uint4*)(Ah + ga);
            *(uint4*)(smem + SM_AL + sw) = *(const uint4*)(Al + ga);
            *(uint4*)(smem + SM_BH + sw) = *(const uint4*)(Wh + gb);
            *(uint4*)(smem + SM_BL + sw) = *(const uint4*)(Wl + gb);
        }
        __syncthreads();

        #pragma unroll
        for (int ks = 0; ks < 4; ks++) {
            int ach = (ks * 2 + a_ch) ^ (a_row & 7);
            int bch = (ks * 2 + b_ch) ^ (b_row & 7);
            uint32_t ah[4][4], bh[4][2], bl[4][2], al[4][4];
            #pragma unroll
            for (int i = 0; i < 4; i++)
                ldsm_x4(ah[i], smem_b + SM_AH + (a_row + i * 16) * 128 + ach * 16);
            #pragma unroll
            for (int j = 0; j < 4; j++)
                ldsm_x2(bh[j], smem_b + SM_BH + (b_row + j * 8) * 128 + bch * 16);
            #pragma unroll
            for (int i = 0; i < 4; i++)
                #pragma unroll
                for (int j = 0; j < 4; j++) mma_bf16(d[i][j], ah[i], bh[j]);
            #pragma unroll
            for (int j = 0; j < 4; j++)
                ldsm_x2(bl[j], smem_b + SM_BL + (b_row + j * 8) * 128 + bch * 16);
            #pragma unroll
            for (int i = 0; i < 4; i++)
                #pragma unroll
                for (int j = 0; j < 4; j++) mma_bf16(d[i][j], ah[i], bl[j]);
            #pragma unroll
            for (int i = 0; i < 4; i++)
                ldsm_x4(al[i], smem_b + SM_AL + (a_row + i * 16) * 128 + ach * 16);
            #pragma unroll
            for (int i = 0; i < 4; i++)
                #pragma unroll
                for (int j = 0; j < 4; j++) mma_bf16(d[i][j], al[i], bh[j]);
        }
    }

    int fr = lane >> 2, fc = (lane & 3) * 2;
    #pragma unroll
    for (int i = 0; i < 4; i++) {
        #pragma unroll
        for (int j = 0; j < 4; j++) {
            int gc = n0 + wn0 + j * 8 + fc;
            float b0 = bias[gc], b1 = bias[gc + 1];
            #pragma unroll
            for (int hh = 0; hh < 2; hh++) {
                int gr = m0 + wm0 + i * 16 + fr + hh * 8;
                float v0 = d[i][j][hh * 2 + 0] + b0;
                float v1 = d[i][j][hh * 2 + 1] + b1;
                __nv_bfloat162 hp, lp;
                hp.x = __float2bfloat16(v0);
                hp.y = __float2bfloat16(v1);
                lp.x = __float2bfloat16(v0 - __bfloat162float(hp.x));
                lp.y = __float2bfloat16(v1 - __bfloat162float(hp.y));
                *(uint32_t*)&outh[(long)gr * 512 + gc] = *(uint32_t*)&hp;
                *(uint32_t*)&outl[(long)gr * 512 + gc] = *(uint32_t*)&lp;
            }
        }
    }
}

// ---------------------------------------------------------------------------
// Attention: one CTA per (b,h). 2 query rows per warp iteration — halves
// ks/vs smem traffic. Per-row FMA order unchanged (bit-identical results).
// ---------------------------------------------------------------------------
__global__ void attn_kernel(const float* __restrict__ qkv,
                            __nv_bfloat16* __restrict__ outh,
                            __nv_bfloat16* __restrict__ outl) {
    int b = blockIdx.x >> 3, h = blockIdx.x & 7;
    extern __shared__ float smemf[];
    float* ks = smemf;                    // 196*65
    float* vs = smemf + 196 * 65;         // 196*65
    float* qs = smemf + 2 * 196 * 65;     // 8*128
    int tid = threadIdx.x;
    const float* base = qkv + b * (196 * 1536) + h * 64;
    for (int idx = tid; idx < 196 * 64; idx += 256) {
        int m = idx >> 6, d = idx & 63;
        ks[m * 65 + d] = base[m * 1536 + 512 + d];
        vs[m * 65 + d] = base[m * 1536 + 1024 + d];
    }
    __syncthreads();
    int w = tid >> 5, lane = tid & 31;
    float* qA = qs + w * 128;
    float* qB = qA + 64;
    for (int l = w; l < 196; l += 16) {
        int lB = l + 8;
        bool hasB = lB < 196;
        qA[lane]      = base[l * 1536 + lane];
        qA[lane + 32] = base[l * 1536 + lane + 32];
        if (hasB) {
            qB[lane]      = base[lB * 1536 + lane];
            qB[lane + 32] = base[lB * 1536 + lane + 32];
        }
        __syncwarp();
        float sA[7], sB[7];
        #pragma unroll
        for (int j = 0; j < 7; j++) {
            int m = j * 32 + lane;
            if (m < 196) {
                float aA = 0.f, aB = 0.f;
                #pragma unroll
                for (int d = 0; d < 64; d++) {
                    float kv = ks[m * 65 + d];
                    aA += qA[d] * kv;
                    aB += qB[d] * kv;
                }
                sA[j] = aA * 0.125f;
                sB[j] = aB * 0.125f;
            } else { sA[j] = -INFINITY; sB[j] = -INFINITY; }
        }
        // softmax A
        float mxA = sA[0], mxB = sB[0];
        #pragma unroll
        for (int j = 1; j < 7; j++) { mxA = fmaxf(mxA, sA[j]); mxB = fmaxf(mxB, sB[j]); }
        #pragma unroll
        for (int off = 16; off; off >>= 1) {
            mxA = fmaxf(mxA, __shfl_xor_sync(0xffffffffu, mxA, off));
            mxB = fmaxf(mxB, __shfl_xor_sync(0xffffffffu, mxB, off));
        }
        float sumA = 0.f, sumB = 0.f;
        #pragma unroll
        for (int j = 0; j < 7; j++) {
            sA[j] = expf(sA[j] - mxA); sumA += sA[j];
            sB[j] = expf(sB[j] - mxB); sumB += sB[j];
        }
        #pragma unroll
        for (int off = 16; off; off >>= 1) {
            sumA += __shfl_xor_sync(0xffffffffu, sumA, off);
            sumB += __shfl_xor_sync(0xffffffffu, sumB, off);
        }
        float invA = 1.f / sumA, invB = 1.f / sumB;
        float o0A = 0.f, o1A = 0.f, o0B = 0.f, o1B = 0.f;
        #pragma unroll
        for (int j = 0; j < 7; j++) {
            #pragma unroll
            for (int mm = 0; mm < 32; mm++) {
                int m = j * 32 + mm;
                if (m >= 196) break;
                float pA = __shfl_sync(0xffffffffu, sA[j], mm);
                float pB = __shfl_sync(0xffffffffu, sB[j], mm);
                float v0 = vs[m * 65 + lane];
                float v1 = vs[m * 65 + lane + 32];
                o0A += pA * v0; o1A += pA * v1;
                o0B += pB * v0; o1B += pB * v1;
            }
        }
        {
            int r = b * 196 + l;
            float x0 = o0A * invA, x1 = o1A * invA;
            long i0 = (long)r * 512 + h * 64 + lane;
            __nv_bfloat16 h0 = __float2bfloat16(x0);
            __nv_bfloat16 h1 = __float2bfloat16(x1);
            outh[i0]      = h0;
            outh[i0 + 32] = h1;
            outl[i0]      = __float2bfloat16(x0 - __bfloat162float(h0));
            outl[i0 + 32] = __float2bfloat16(x1 - __bfloat162float(h1));
        }
        if (hasB) {
            int r = b * 196 + lB;
            float x0 = o0B * invB, x1 = o1B * invB;
            long i0 = (long)r * 512 + h * 64 + lane;
            __nv_bfloat16 h0 = __float2bfloat16(x0);
            __nv_bfloat16 h1 = __float2bfloat16(x1);
            outh[i0]      = h0;
            outh[i0 + 32] = h1;
            outl[i0]      = __float2bfloat16(x0 - __bfloat162float(h0));
            outl[i0 + 32] = __float2bfloat16(x1 - __bfloat162float(h1));
        }
        __syncwarp();
    }
}

// ---------------------------------------------------------------------------
// Pair kernel via mma.sync bf16x3 with fused row/col max epilogue.
// 2-stage cp.async pipeline (2 x 64KB smem buffers) — identical mma sequence.
// ---------------------------------------------------------------------------
#define PK_SMEM 131072
#define PK_BUF  65536

__global__ void __launch_bounds__(256) pair_mma_kernel(
        const __nv_bfloat16* __restrict__ QLh, const __nv_bfloat16* __restrict__ QLl,
        const __nv_bfloat16* __restrict__ KLh, const __nv_bfloat16* __restrict__ KLl,
        unsigned* __restrict__ rowparts, unsigned* __restrict__ colparts) {
    extern __shared__ char smem[];
    float (*Ct)[130] = (float(*)[130])smem;
    int tid = threadIdx.x;
    int wid = tid >> 5, lane = tid & 31;
    int m0 = blockIdx.y * 128, n0 = blockIdx.x * 128;
    int wm0 = (wid >> 2) * 64, wn0 = (wid & 3) * 32;

    int a_row = wm0 + (lane & 15);
    int a_ch  = (lane >> 4);
    int b_row = wn0 + (lane & 7);
    int b_ch  = ((lane >> 3) & 1);
    uint32_t smem_b = smem_u32(smem);

    float d[4][4][4];
    #pragma unroll
    for (int i = 0; i < 4; i++)
        #pragma unroll
        for (int j = 0; j < 4; j++)
            #pragma unroll
            for (int q = 0; q < 4; q++) d[i][j][q] = 0.f;

    // stage chunk kc into buffer buf via cp.async (one commit group)
    auto stage = [&](int kc, int buf) {
        uint32_t b0 = smem_b + buf * PK_BUF;
        #pragma unroll
        for (int t = 0; t < 4; t++) {
            int s2 = tid + t * 256;
            int row = s2 >> 3, sc = s2 & 7;
            uint32_t sw = SWZ128((uint32_t)(row * 128 + sc * 16));
            long ga = (long)(m0 + row) * 512 + kc * 64 + sc * 8;
            long gb = (long)(n0 + row) * 512 + kc * 64 + sc * 8;
            cp_async16(b0 + SM_AH + sw, QLh + ga);
            cp_async16(b0 + SM_AL + sw, QLl + ga);
            cp_async16(b0 + SM_BH + sw, KLh + gb);
            cp_async16(b0 + SM_BL + sw, KLl + gb);
        }
        cp_commit();
    };

    stage(0, 0);
    for (int kc = 0; kc < 8; kc++) {
        if (kc < 7) stage(kc + 1, (kc + 1) & 1);
        if (kc < 7) cp_wait<1>(); else cp_wait<0>();
        __syncthreads();
        uint32_t bofs = (uint32_t)((kc & 1) * PK_BUF);

        #pragma unroll
        for (int ks = 0; ks < 4; ks++) {
            int ach = (ks * 2 + a_ch) ^ (a_row & 7);
            int bch = (ks * 2 + b_ch) ^ (b_row & 7);
            uint32_t ah[4][4], bh[4][2], bl[4][2], al[4][4];
            #pragma unroll
            for (int i = 0; i < 4; i++)
                ldsm_x4(ah[i], smem_b + bofs + SM_AH + (a_row + i * 16) * 128 + ach * 16);
            #pragma unroll
            for (int j = 0; j < 4; j++)
                ldsm_x2(bh[j], smem_b + bofs + SM_BH + (b_row + j * 8) * 128 + bch * 16);
            #pragma unroll
            for (int i = 0; i < 4; i++)
                #pragma unroll
                for (int j = 0; j < 4; j++) mma_bf16(d[i][j], ah[i], bh[j]);
            #pragma unroll
            for (int j = 0; j < 4; j++)
                ldsm_x2(bl[j], smem_b + bofs + SM_BL + (b_row + j * 8) * 128 + bch * 16);
            #pragma unroll
            for (int i = 0; i < 4; i++)
                #pragma unroll
                for (int j = 0; j < 4; j++) mma_bf16(d[i][j], ah[i], bl[j]);
            #pragma unroll
            for (int i = 0; i < 4; i++)
                ldsm_x4(al[i], smem_b + bofs + SM_AL + (a_row + i * 16) * 128 + ach * 16);
            #pragma unroll
            for (int i = 0; i < 4; i++)
                #pragma unroll
                for (int j = 0; j < 4; j++) mma_bf16(d[i][j], al[i], bh[j]);
        }
        __syncthreads();
    }

    int fr = lane >> 2, fc = (lane & 3) * 2;
    #pragma unroll
    for (int i = 0; i < 4; i++) {
        #pragma unroll
        for (int j = 0; j < 4; j++) {
            int r = wm0 + i * 16 + fr, c = wn0 + j * 8 + fc;
            *(float2*)&Ct[r][c]     = make_float2(d[i][j][0], d[i][j][1]);
            *(float2*)&Ct[r + 8][c] = make_float2(d[i][j][2], d[i][j][3]);
        }
    }
    __syncthreads();

    if (tid < 128) {
        int r = tid, gr = m0 + r;
        int b0 = n0 / 196;
        int bnd = (b0 + 1) * 196 - n0;
        if (bnd > 128) bnd = 128;
        float m1 = -INFINITY, m2 = -INFINITY;
        for (int c = 0; c < 128; c++) {
            float v = Ct[r][c];
            if (c < bnd) m1 = fmaxf(m1, v); else m2 = fmaxf(m2, v);
        }
        atomicMax(&rowparts[b0 * 6272 + gr], enc_f(m1));
        if (bnd < 128)
            atomicMax(&rowparts[(b0 + 1) * 6272 + gr], enc_f(m2));
    } else {
        int c = tid - 128, gc = n0 + c;
        int a0 = m0 / 196;
        int bnd = (a0 + 1) * 196 - m0;
        if (bnd > 128) bnd = 128;
        float m1 = -INFINITY, m2 = -INFINITY;
        for (int r = 0; r < 128; r++) {
            float v = Ct[r][c];
            if (r < bnd) m1 = fmaxf(m1, v); else m2 = fmaxf(m2, v);
        }
        atomicMax(&colparts[a0 * 6272 + gc], enc_f(m1));
        if (bnd < 128)
            atomicMax(&colparts[(a0 + 1) * 6272 + gc], enc_f(m2));
    }
}

// ---------------------------------------------------------------------------
__global__ void reduce_s_kernel(const unsigned* __restrict__ rowparts,
                                const unsigned* __restrict__ colparts,
                                const float* __restrict__ logit_scale,
                                float* __restrict__ S) {
    int pair = blockIdx.x, tid = threadIdx.x;
    int a = pair >> 5, b = pair & 31;
    float s = 0.f;
    for (int l = tid; l < 196; l += 256)
        s += dec_f(rowparts[b * 6272 + a * 196 + l]);
    for (int m = tid; m < 196; m += 256)
        s += dec_f(colparts[a * 6272 + b * 196 + m]);
    __shared__ float red[256];
    red[tid] = s;
    __syncthreads();
    for (int st = 128; st; st >>= 1) {
        if (tid < st) red[tid] += red[tid + st];
        __syncthreads();
    }
    if (tid == 0) S[pair] = 0.5f * red[0] * (1.f / 196.f) * expf(logit_scale[0]);
}

__global__ void loss_kernel(const float* __restrict__ S, float* __restrict__ out) {
    int tid = threadIdx.x;
    int w = tid >> 5, lane = tid & 31;
    float rv = S[w * 32 + lane];
    float cv = S[lane * 32 + w];
    float rm = rv, cm = cv;
    #pragma unroll
    for (int off = 16; off; off >>= 1) {
        rm = fmaxf(rm, __shfl_xor_sync(0xffffffffu, rm, off));
        cm = fmaxf(cm, __shfl_xor_sync(0xffffffffu, cm, off));
    }
    float re = expf(rv - rm), cex = expf(cv - cm);
    #pragma unroll
    for (int off = 16; off; off >>= 1) {
        re  += __shfl_xor_sync(0xffffffffu, re, off);
        cex += __shfl_xor_sync(0xffffffffu, cex, off);
    }
    __shared__ float acc[32];
    if (lane == 0) {
        float dg = S[w * 33];
        acc[w] = (dg - (rm + logf(re))) + (dg - (cm + logf(cex)));
    }
    __syncthreads();
    if (tid == 0) {
        float t = 0.f;
        for (int i = 0; i < 32; i++) t += acc[i];
        out[0] = -0.5f * t * (1.f / 32.f);
    }
}

// ---------------------------------------------------------------------------
extern "C" void kernel_launch(void* const* d_in, const int* in_sizes, int n_in,
                              void* d_out, int out_size) {
    const float* bef        = (const float*)d_in[0];
    const float* sentf      = (const float*)d_in[1];
    const float* aft        = (const float*)d_in[2];
    const float* masks      = (const float*)d_in[3];
    const float* conv1_w    = (const float*)d_in[4];
    const float* conv1_b    = (const float*)d_in[5];
    const float* in_proj_w  = (const float*)d_in[6];
    const float* out_proj_w = (const float*)d_in[7];
    const float* conv2_w    = (const float*)d_in[8];
    const float* conv2_b    = (const float*)d_in[9];
    const float* q_w        = (const float*)d_in[10];
    const float* q_b        = (const float*)d_in[11];
    const float* k_w        = (const float*)d_in[12];
    const float* k_b        = (const float*)d_in[13];
    const float* logit_scale= (const float*)d_in[14];

    float* base = nullptr;
    cudaGetSymbolAddress((void**)&base, g_buf);
    float* p_sm  = base + OFF_SM;
    float* p_b2  = base + OFF_B2;
    float* p_bq  = base + OFF_BQ;
    float* p_w67 = base + OFF_W67;
    float* p_wq  = base + OFF_WQ;
    float* p_S   = base + OFF_S;
    float* p_v1  = base + OFF_V1;
    float* p_qkv = base + OFF_QKV;
    unsigned* p_rp = (unsigned*)(base + OFF_RP);
    unsigned* p_cp = (unsigned*)(base + OFF_CP);
    #define BF16P(off) ((__nv_bfloat16*)(base + (off)))
    __nv_bfloat16* aoh  = BF16P(OFF_AOH);  __nv_bfloat16* aol  = BF16P(OFF_AOL);
    __nv_bfloat16* afth = BF16P(OFF_AFTH); __nv_bfloat16* aftl = BF16P(OFF_AFTL);
    __nv_bfloat16* qlh  = BF16P(OFF_QLH);  __nv_bfloat16* qll  = BF16P(OFF_QLL);
    __nv_bfloat16* klh  = BF16P(OFF_KLH);  __nv_bfloat16* kll  = BF16P(OFF_KLL);
    __nv_bfloat16* wqh  = BF16P(OFF_WQH);  __nv_bfloat16* wql  = BF16P(OFF_WQL);
    __nv_bfloat16* kwh  = BF16P(OFF_KWH);  __nv_bfloat16* kwl  = BF16P(OFF_KWL);

    cudaFuncSetAttribute(mma_gemm_b1, cudaFuncAttributeMaxDynamicSharedMemorySize, MG_SMEM);
    cudaFuncSetAttribute(pair_mma_kernel, cudaFuncAttributeMaxDynamicSharedMemorySize, PK_SMEM);

    // prep: text mean, per-batch conv1 bias, init partials, aft/k_w splits
    sent_mean_kernel<<<32, 512>>>(sentf, masks, p_sm);
    bias2_kernel<<<2048, 256>>>(conv1_w, conv1_b, p_sm, p_b2);
    init_parts_kernel<<<256, 256>>>(p_rp, 2 * 200704);
    split_str_kernel<<<1024, 256>>>(aft, afth, aftl, 6272 * 512, 512);
    split_str_kernel<<<256, 256>>>(k_w, kwh, kwl, 512 * 512, 512);

    // v1 = bef @ conv1_w[:, :512]^T + bias2[b]   (exact fp32)
    gemm128<2><<<dim3(4, 49), 256>>>(bef, conv1_w, p_v1, p_b2, 512, 512, 1024, 512);
    // qkv = v1 @ in_proj_w^T                     (exact fp32)
    gemm128<0><<<dim3(12, 49), 256>>>(p_v1, in_proj_w, p_qkv, nullptr, 512, 512, 512, 1536);

    size_t attn_smem = (2 * 196 * 65 + 8 * 128) * sizeof(float);
    cudaFuncSetAttribute(attn_kernel, cudaFuncAttributeMaxDynamicSharedMemorySize, (int)attn_smem);
    attn_kernel<<<256, 256, attn_smem>>>(p_qkv, aoh, aol);

    // fused weights: Wq = q_w @ conv2_w @ out_proj_w ; bq = q_b + q_w@conv2_b
    gemm64_nt<<<dim3(8, 8), 256>>>(conv2_w, out_proj_w, p_w67, 512, 512, 512, 512);
    gemm64_nt<<<dim3(8, 8), 256>>>(q_w, p_w67, p_wq, 512, 512, 512, 512);
    bq_kernel<<<1, 512>>>(q_w, conv2_b, q_b, p_bq);
    split_str_kernel<<<256, 256>>>(p_wq, wqh, wql, 512 * 512, 512);

    // QL = ao @ Wq^T + bq ; KL = aft @ k_w^T + k_b   (bf16x3 mma, split out)
    mma_gemm_b1<<<dim3(4, 49), 256, MG_SMEM>>>(aoh, aol, wqh, wql, qlh, qll, p_bq);
    mma_gemm_b1<<<dim3(4, 49), 256, MG_SMEM>>>(afth, aftl, kwh, kwl, klh, kll, k_b);

    // pair GEMM + fused max epilogue (cp.async double-buffered)
    pair_mma_kernel<<<dim3(49, 49), 256, PK_SMEM>>>(qlh, qll, klh, kll, p_rp, p_cp);

    reduce_s_kernel<<<1024, 256>>>(p_rp, p_cp, logit_scale, p_S);
    loss_kernel<<<1, 1024>>>(p_S, (float*)d_out);
}

// round 10
// speedup vs baseline: 3.7583x; 1.1637x over previous
#include <cuda_runtime.h>
#include <cuda_bf16.h>
#include <math.h>
#include <stdint.h>

// Shapes fixed: B=32, LV=196, LT=40, D=512, H=8, DH=64, R=B*LV=6272 (=49*128)

// ---------------------------------------------------------------------------
// Scratch buffer layout (float slots) — identical to round 7/9
// ---------------------------------------------------------------------------
#define OFF_SM    0u
#define OFF_B2    16384u
#define OFF_BQ    32768u
#define OFF_W67   33280u
#define OFF_WQ    295424u
#define OFF_S     557568u
#define OFF_RP    558592u
#define OFF_CP    759296u
#define OFF_V1    960000u
#define OFF_QKV   4171264u
#define OFF_AOH   13805056u
#define OFF_AOL   15410688u
#define OFF_AFTH  17016320u
#define OFF_AFTL  18621952u
#define OFF_QLH   20227584u
#define OFF_QLL   21833216u
#define OFF_KLH   23438848u
#define OFF_KLL   25044480u
#define OFF_WQH   26650112u
#define OFF_WQL   26715648u
#define OFF_KWH   26781184u
#define OFF_KWL   26846720u
#define TOTAL_F   26912256u

__device__ __align__(256) float g_buf[TOTAL_F];

// ---------------------------------------------------------------------------
// mma.sync / ldmatrix / cp.async helpers
// ---------------------------------------------------------------------------
__device__ __forceinline__ uint32_t smem_u32(const void* p) {
    uint32_t a;
    asm("{ .reg .u64 t; cvta.to.shared.u64 t, %1; cvt.u32.u64 %0, t; }" : "=r"(a) : "l"(p));
    return a;
}
__device__ __forceinline__ void ldsm_x4(uint32_t* r, uint32_t addr) {
    asm volatile("ldmatrix.sync.aligned.m8n8.x4.shared.b16 {%0,%1,%2,%3}, [%4];"
                 : "=r"(r[0]), "=r"(r[1]), "=r"(r[2]), "=r"(r[3]) : "r"(addr));
}
__device__ __forceinline__ void ldsm_x2(uint32_t* r, uint32_t addr) {
    asm volatile("ldmatrix.sync.aligned.m8n8.x2.shared.b16 {%0,%1}, [%2];"
                 : "=r"(r[0]), "=r"(r[1]) : "r"(addr));
}
__device__ __forceinline__ void mma_bf16(float* d, const uint32_t* a, const uint32_t* b) {
    asm volatile("mma.sync.aligned.m16n8k16.row.col.f32.bf16.bf16.f32 "
                 "{%0,%1,%2,%3}, {%4,%5,%6,%7}, {%8,%9}, {%0,%1,%2,%3};"
                 : "+f"(d[0]), "+f"(d[1]), "+f"(d[2]), "+f"(d[3])
                 : "r"(a[0]), "r"(a[1]), "r"(a[2]), "r"(a[3]), "r"(b[0]), "r"(b[1]));
}
__device__ __forceinline__ void cp_async16(uint32_t dst, const void* src) {
    asm volatile("cp.async.cg.shared.global [%0], [%1], 16;" :: "r"(dst), "l"(src) : "memory");
}
__device__ __forceinline__ void cp_commit() {
    asm volatile("cp.async.commit_group;" ::: "memory");
}
template<int N>
__device__ __forceinline__ void cp_wait() {
    asm volatile("cp.async.wait_group %0;" :: "n"(N) : "memory");
}
#define SWZ128(off) ((off) ^ (((off) >> 3) & 0x70))

__device__ __forceinline__ unsigned enc_f(float f) {
    unsigned u = __float_as_uint(f);
    return u ^ ((((int)u >> 31)) | 0x80000000u);
}
__device__ __forceinline__ float dec_f(unsigned u) {
    unsigned m = (u & 0x80000000u) ? 0x80000000u : 0xFFFFFFFFu;
    return __uint_as_float(u ^ m);
}

// ---------------------------------------------------------------------------
__global__ void sent_mean_kernel(const float* __restrict__ sentf,
                                 const float* __restrict__ masks,
                                 float* __restrict__ sm) {
    int b = blockIdx.x, d = threadIdx.x;
    float s = 0.f;
    #pragma unroll
    for (int t = 0; t < 40; t++)
        s += sentf[(b * 40 + t) * 512 + d] * masks[b * 40 + t];
    sm[b * 512 + d] = s * (1.f / 40.f);
}

__global__ void bias2_kernel(const float* __restrict__ conv1_w,
                             const float* __restrict__ conv1_b,
                             const float* __restrict__ sm,
                             float* __restrict__ b2) {
    int gw = (blockIdx.x * blockDim.x + threadIdx.x) >> 5;
    int lane = threadIdx.x & 31;
    int b = gw >> 9, o = gw & 511;
    const float* wrow = conv1_w + o * 1024 + 512;
    const float* srow = sm + b * 512;
    float s = 0.f;
    for (int c = lane; c < 512; c += 32) s += wrow[c] * srow[c];
    #pragma unroll
    for (int off = 16; off; off >>= 1) s += __shfl_xor_sync(0xffffffffu, s, off);
    if (lane == 0) b2[b * 512 + o] = conv1_b[o] + s;
}

// warp-per-output: bq[q] = q_b[q] + sum_o q_w[q,o]*conv2_b[o]
__global__ void bq_kernel(const float* __restrict__ q_w,
                          const float* __restrict__ conv2_b,
                          const float* __restrict__ q_b,
                          float* __restrict__ bq) {
    int gw = blockIdx.x * 8 + (threadIdx.x >> 5);
    int lane = threadIdx.x & 31;
    const float* row = q_w + gw * 512;
    float s = 0.f;
    for (int c = lane; c < 512; c += 32) s += row[c] * conv2_b[c];
    #pragma unroll
    for (int off = 16; off; off >>= 1) s += __shfl_xor_sync(0xffffffffu, s, off);
    if (lane == 0) bq[gw] = q_b[gw] + s;
}

// ---------------------------------------------------------------------------
// Small fp32 GEMM for 512x512x512 weight fusions. C = A*B (both row-major).
// ---------------------------------------------------------------------------
__global__ void gemm64_nt(const float* __restrict__ A, const float* __restrict__ B,
                          float* __restrict__ C, int K, int lda, int ldb, int ldc) {
    __shared__ float As[32][65];
    __shared__ float Bs[32][65];
    int tid = threadIdx.x;
    int tx = tid & 15, ty = tid >> 4;
    int n0 = blockIdx.x * 64, m0 = blockIdx.y * 64;
    float acc[4][4] = {};
    for (int k0 = 0; k0 < K; k0 += 32) {
        #pragma unroll
        for (int i = 0; i < 8; i++) {
            int idx = tid + i * 256;
            int k = idx & 31, r = idx >> 5;
            As[k][r] = A[(m0 + r) * lda + k0 + k];
            int n = idx & 63, kk = idx >> 6;
            Bs[kk][n] = B[(k0 + kk) * ldb + n0 + n];
        }
        __syncthreads();
        #pragma unroll
        for (int k = 0; k < 32; k++) {
            float ar[4], br[4];
            #pragma unroll
            for (int i = 0; i < 4; i++) ar[i] = As[k][ty * 4 + i];
            #pragma unroll
            for (int j = 0; j < 4; j++) br[j] = Bs[k][tx * 4 + j];
            #pragma unroll
            for (int i = 0; i < 4; i++)
                #pragma unroll
                for (int j = 0; j < 4; j++) acc[i][j] += ar[i] * br[j];
        }
        __syncthreads();
    }
    #pragma unroll
    for (int i = 0; i < 4; i++)
        #pragma unroll
        for (int j = 0; j < 4; j++)
            C[(m0 + ty * 4 + i) * ldc + n0 + tx * 4 + j] = acc[i][j];
}

// ---------------------------------------------------------------------------
// fp32 SIMT GEMM: C = A(MxK) * B(NxK)^T, 128x128 tile, 8x8 micro, BK=8, dbuf.
// MODE 0: plain. MODE 2: +bias[(r/196)*512+n].
// ---------------------------------------------------------------------------
template<int MODE>
__global__ void __launch_bounds__(256) gemm128(
        const float* __restrict__ A, const float* __restrict__ B,
        float* __restrict__ C, const float* __restrict__ bias,
        int K, int lda, int ldb, int ldc) {
    __shared__ float As[2][8][132];
    __shared__ float Bs[2][8][132];
    int tid = threadIdx.x;
    int tx = tid & 15, ty = tid >> 4;
    int row = tid >> 1, seg = tid & 1;
    int m0 = blockIdx.y * 128, n0 = blockIdx.x * 128;

    const float* Abase = A + (m0 + row) * lda + seg * 4;
    const float* Bbase = B + (n0 + row) * ldb + seg * 4;

    float acc[8][8] = {};
    float4 pa = *(const float4*)Abase;
    float4 pb = *(const float4*)Bbase;
    As[0][seg * 4 + 0][row] = pa.x; As[0][seg * 4 + 1][row] = pa.y;
    As[0][seg * 4 + 2][row] = pa.z; As[0][seg * 4 + 3][row] = pa.w;
    Bs[0][seg * 4 + 0][row] = pb.x; Bs[0][seg * 4 + 1][row] = pb.y;
    Bs[0][seg * 4 + 2][row] = pb.z; Bs[0][seg * 4 + 3][row] = pb.w;
    __syncthreads();

    int NK = K >> 3;
    for (int kt = 0; kt < NK; kt++) {
        int cur = kt & 1;
        if (kt + 1 < NK) {
            pa = *(const float4*)(Abase + (kt + 1) * 8);
            pb = *(const float4*)(Bbase + (kt + 1) * 8);
        }
        #pragma unroll
        for (int k = 0; k < 8; k++) {
            float ar[8], br[8];
            *(float4*)(ar)     = *(const float4*)&As[cur][k][ty * 4];
            *(float4*)(ar + 4) = *(const float4*)&As[cur][k][64 + ty * 4];
            *(float4*)(br)     = *(const float4*)&Bs[cur][k][tx * 4];
            *(float4*)(br + 4) = *(const float4*)&Bs[cur][k][64 + tx * 4];
            #pragma unroll
            for (int i = 0; i < 8; i++)
                #pragma unroll
                for (int j = 0; j < 8; j++)
                    acc[i][j] += ar[i] * br[j];
        }
        if (kt + 1 < NK) {
            int nxt = cur ^ 1;
            As[nxt][seg * 4 + 0][row] = pa.x; As[nxt][seg * 4 + 1][row] = pa.y;
            As[nxt][seg * 4 + 2][row] = pa.z; As[nxt][seg * 4 + 3][row] = pa.w;
            Bs[nxt][seg * 4 + 0][row] = pb.x; Bs[nxt][seg * 4 + 1][row] = pb.y;
            Bs[nxt][seg * 4 + 2][row] = pb.z; Bs[nxt][seg * 4 + 3][row] = pb.w;
        }
        __syncthreads();
    }

    #pragma unroll
    for (int i = 0; i < 8; i++) {
        int r = m0 + ty * 4 + (i & 3) + ((i >> 2) << 6);
        int boff = (MODE == 2) ? (r / 196) * 512 : 0;
        #pragma unroll
        for (int hj = 0; hj < 2; hj++) {
            int c = n0 + tx * 4 + (hj << 6);
            float4 v;
            v.x = acc[i][hj * 4 + 0]; v.y = acc[i][hj * 4 + 1];
            v.z = acc[i][hj * 4 + 2]; v.w = acc[i][hj * 4 + 3];
            if (MODE == 2) {
                v.x += bias[boff + c]; v.y += bias[boff + c + 1];
                v.z += bias[boff + c + 2]; v.w += bias[boff + c + 3];
            }
            *(float4*)&C[r * ldc + c] = v;
        }
    }
}

// ---------------------------------------------------------------------------
// Vectorized split: hi = bf16(x), lo = bf16(x - hi). Contiguous, n % 4 == 0.
// Same per-element rounding as scalar version (bit-identical outputs).
// ---------------------------------------------------------------------------
__global__ void split_vec_kernel(const float4* __restrict__ src,
                                 uint2* __restrict__ hi,
                                 uint2* __restrict__ lo, int n4) {
    for (int i = blockIdx.x * blockDim.x + threadIdx.x; i < n4; i += gridDim.x * blockDim.x) {
        float4 x = src[i];
        __nv_bfloat162 h0, h1, l0, l1;
        h0.x = __float2bfloat16(x.x); h0.y = __float2bfloat16(x.y);
        h1.x = __float2bfloat16(x.z); h1.y = __float2bfloat16(x.w);
        l0.x = __float2bfloat16(x.x - __bfloat162float(h0.x));
        l0.y = __float2bfloat16(x.y - __bfloat162float(h0.y));
        l1.x = __float2bfloat16(x.z - __bfloat162float(h1.x));
        l1.y = __float2bfloat16(x.w - __bfloat162float(h1.y));
        hi[i] = make_uint2(*(uint32_t*)&h0, *(uint32_t*)&h1);
        lo[i] = make_uint2(*(uint32_t*)&l0, *(uint32_t*)&l1);
    }
}

__global__ void init_parts_kernel(unsigned* __restrict__ p, int n) {
    for (int i = blockIdx.x * blockDim.x + threadIdx.x; i < n; i += gridDim.x * blockDim.x)
        p[i] = 0x007FFFFFu;   // enc(-inf)
}

// ---------------------------------------------------------------------------
// bf16x3 mma GEMM (MODE 1): C[M,N] = A(Mx512)@W(Nx512)^T + bias[n],
// output as bf16 hi/lo splits. 128x128 CTA tile, 8 warps x (64x32).
// ---------------------------------------------------------------------------
#define MG_SMEM 65536
#define SM_AH 0
#define SM_AL 16384
#define SM_BH 32768
#define SM_BL 49152

__global__ void __launch_bounds__(256) mma_gemm_b1(
        const __nv_bfloat16* __restrict__ Ah, const __nv_bfloat16* __restrict__ Al,
        const __nv_bfloat16* __restrict__ Wh, const __nv_bfloat16* __restrict__ Wl,
        __nv_bfloat16* __restrict__ outh, __nv_bfloat16* __restrict__ outl,
        const float* __restrict__ bias) {
    extern __shared__ char smem[];
    int tid = threadIdx.x;
    int wid = tid >> 5, lane = tid & 31;
    int m0 = blockIdx.y * 128, n0 = blockIdx.x * 128;
    int wm0 = (wid >> 2) * 64, wn0 = (wid & 3) * 32;

    int a_row = wm0 + (lane & 15);
    int a_ch  = (lane >> 4);
    int b_row = wn0 + (lane & 7);
    int b_ch  = ((lane >> 3) & 1);
    uint32_t smem_b = smem_u32(smem);

    float d[4][4][4];
    #pragma unroll
    for (int i = 0; i < 4; i++)
        #pragma unroll
        for (int j = 0; j < 4; j++)
            #pragma unroll
            for (int q = 0; q < 4; q++) d[i][j][q] = 0.f;

    for (int kc = 0; kc < 8; kc++) {
        __syncthreads();
        #pragma unroll
        for (int t = 0; t < 4; t++) {
            int s2 = tid + t * 256;
            int row = s2 >> 3, sc = s2 & 7;
            uint32_t sw = SWZ128((uint32_t)(row * 128 + sc * 16));
            long ga = (long)(m0 + row) * 512 + kc * 64 + sc * 8;
            long gb = (long)(n0 + row) * 512 + kc * 64 + sc * 8;
            *(uint4*)(smem + SM_AH + sw) = *(const uint4*)(Ah + ga);
            *(uint4*)(smem + SM_AL + sw) = *(const uint4*)(Al + ga);
            *(uint4*)(smem + SM_BH + sw) = *(const uint4*)(Wh + gb);
            *(uint4*)(smem + SM_BL + sw) = *(const uint4*)(Wl + gb);
        }
        __syncthreads();

        #pragma unroll
        for (int ks = 0; ks < 4; ks++) {
            int ach = (ks * 2 + a_ch) ^ (a_row & 7);
            int bch = (ks * 2 + b_ch) ^ (b_row & 7);
            uint32_t ah[4][4], bh[4][2], bl[4][2], al[4][4];
            #pragma unroll
            for (int i = 0; i < 4; i++)
                ldsm_x4(ah[i], smem_b + SM_AH + (a_row + i * 16) * 128 + ach * 16);
            #pragma unroll
            for (int j = 0; j < 4; j++)
                ldsm_x2(bh[j], smem_b + SM_BH + (b_row + j * 8) * 128 + bch * 16);
            #pragma unroll
            for (int i = 0; i < 4; i++)
                #pragma unroll
                for (int j = 0; j < 4; j++) mma_bf16(d[i][j], ah[i], bh[j]);
            #pragma unroll
            for (int j = 0; j < 4; j++)
                ldsm_x2(bl[j], smem_b + SM_BL + (b_row + j * 8) * 128 + bch * 16);
            #pragma unroll
            for (int i = 0; i < 4; i++)
                #pragma unroll
                for (int j = 0; j < 4; j++) mma_bf16(d[i][j], ah[i], bl[j]);
            #pragma unroll
            for (int i = 0; i < 4; i++)
                ldsm_x4(al[i], smem_b + SM_AL + (a_row + i * 16) * 128 + ach * 16);
            #pragma unroll
            for (int i = 0; i < 4; i++)
                #pragma unroll
                for (int j = 0; j < 4; j++) mma_bf16(d[i][j], al[i], bh[j]);
        }
    }

    int fr = lane >> 2, fc = (lane & 3) * 2;
    #pragma unroll
    for (int i = 0; i < 4; i++) {
        #pragma unroll
        for (int j = 0; j < 4; j++) {
            int gc = n0 + wn0 + j * 8 + fc;
            float b0 = bias[gc], b1 = bias[gc + 1];
            #pragma unroll
            for (int hh = 0; hh < 2; hh++) {
                int gr = m0 + wm0 + i * 16 + fr + hh * 8;
                float v0 = d[i][j][hh * 2 + 0] + b0;
                float v1 = d[i][j][hh * 2 + 1] + b1;
                __nv_bfloat162 hp, lp;
                hp.x = __float2bfloat16(v0);
                hp.y = __float2bfloat16(v1);
                lp.x = __float2bfloat16(v0 - __bfloat162float(hp.x));
                lp.y = __float2bfloat16(v1 - __bfloat162float(hp.y));
                *(uint32_t*)&outh[(long)gr * 512 + gc] = *(uint32_t*)&hp;
                *(uint32_t*)&outl[(long)gr * 512 + gc] = *(uint32_t*)&lp;
            }
        }
    }
}

// ---------------------------------------------------------------------------
// Attention: one CTA per (b,h). 4 query rows per warp iteration, QK loop
// restructured d-outer (7 ks + 4 q loads feed 28 FMAs). Per-row accumulation
// order unchanged (d ascending; PV j,mm ascending) — bit-identical results.
// ---------------------------------------------------------------------------
__global__ void attn_kernel(const float* __restrict__ qkv,
                            __nv_bfloat16* __restrict__ outh,
                            __nv_bfloat16* __restrict__ outl) {
    int b = blockIdx.x >> 3, h = blockIdx.x & 7;
    extern __shared__ float smemf[];
    float* ks = smemf;                    // 196*65
    float* vs = smemf + 196 * 65;         // 196*65
    float* qs = smemf + 2 * 196 * 65;     // 8*256
    int tid = threadIdx.x;
    const float* base = qkv + b * (196 * 1536) + h * 64;
    for (int idx = tid; idx < 196 * 64; idx += 256) {
        int m = idx >> 6, d = idx & 63;
        ks[m * 65 + d] = base[m * 1536 + 512 + d];
        vs[m * 65 + d] = base[m * 1536 + 1024 + d];
    }
    __syncthreads();
    int w = tid >> 5, lane = tid & 31;
    float* q0 = qs + w * 256;

    for (int l0 = w; l0 < 196; l0 += 32) {
        bool has[4];
        #pragma unroll
        for (int rr = 0; rr < 4; rr++) {
            int lr = l0 + rr * 8;
            has[rr] = lr < 196;
            if (has[rr]) {
                q0[rr * 64 + lane]      = base[lr * 1536 + lane];
                q0[rr * 64 + lane + 32] = base[lr * 1536 + lane + 32];
            } else {
                q0[rr * 64 + lane]      = 0.f;
                q0[rr * 64 + lane + 32] = 0.f;
            }
        }
        __syncwarp();

        float s[4][7];
        #pragma unroll
        for (int rr = 0; rr < 4; rr++)
            #pragma unroll
            for (int j = 0; j < 7; j++) s[rr][j] = 0.f;

        for (int d = 0; d < 64; d++) {
            float kv[7];
            #pragma unroll
            for (int j = 0; j < 6; j++) kv[j] = ks[(j * 32 + lane) * 65 + d];
            kv[6] = (lane < 4) ? ks[(192 + lane) * 65 + d] : 0.f;
            #pragma unroll
            for (int rr = 0; rr < 4; rr++) {
                float qv = q0[rr * 64 + d];
                #pragma unroll
                for (int j = 0; j < 7; j++) s[rr][j] += qv * kv[j];
            }
        }
        #pragma unroll
        for (int rr = 0; rr < 4; rr++) {
            #pragma unroll
            for (int j = 0; j < 7; j++) s[rr][j] *= 0.125f;
            if (lane >= 4) s[rr][6] = -INFINITY;
        }

        // per-row softmax (same ops/order as before)
        float inv[4];
        #pragma unroll
        for (int rr = 0; rr < 4; rr++) {
            float mx = s[rr][0];
            #pragma unroll
            for (int j = 1; j < 7; j++) mx = fmaxf(mx, s[rr][j]);
            #pragma unroll
            for (int off = 16; off; off >>= 1)
                mx = fmaxf(mx, __shfl_xor_sync(0xffffffffu, mx, off));
            float sum = 0.f;
            #pragma unroll
            for (int j = 0; j < 7; j++) { s[rr][j] = expf(s[rr][j] - mx); sum += s[rr][j]; }
            #pragma unroll
            for (int off = 16; off; off >>= 1)
                sum += __shfl_xor_sync(0xffffffffu, sum, off);
            inv[rr] = 1.f / sum;
        }

        float o0[4] = {0.f, 0.f, 0.f, 0.f};
        float o1[4] = {0.f, 0.f, 0.f, 0.f};
        #pragma unroll
        for (int j = 0; j < 7; j++) {
            #pragma unroll
            for (int mm = 0; mm < 32; mm++) {
                int m = j * 32 + mm;
                if (m >= 196) break;
                float v0 = vs[m * 65 + lane];
                float v1 = vs[m * 65 + lane + 32];
                #pragma unroll
                for (int rr = 0; rr < 4; rr++) {
                    float p = __shfl_sync(0xffffffffu, s[rr][j], mm);
                    o0[rr] += p * v0;
                    o1[rr] += p * v1;
                }
            }
        }
        #pragma unroll
        for (int rr = 0; rr < 4; rr++) {
            if (!has[rr]) continue;
            int r = b * 196 + l0 + rr * 8;
            float x0 = o0[rr] * inv[rr], x1 = o1[rr] * inv[rr];
            long i0 = (long)r * 512 + h * 64 + lane;
            __nv_bfloat16 h0 = __float2bfloat16(x0);
            __nv_bfloat16 h1 = __float2bfloat16(x1);
            outh[i0]      = h0;
            outh[i0 + 32] = h1;
            outl[i0]      = __float2bfloat16(x0 - __bfloat162float(h0));
            outl[i0 + 32] = __float2bfloat16(x1 - __bfloat162float(h1));
        }
        __syncwarp();
    }
}

// ---------------------------------------------------------------------------
// Pair kernel via mma.sync bf16x3 with fused row/col max epilogue.
// 2-stage cp.async pipeline (2 x 64KB smem buffers).
// ---------------------------------------------------------------------------
#define PK_SMEM 131072
#define PK_BUF  65536

__global__ void __launch_bounds__(256) pair_mma_kernel(
        const __nv_bfloat16* __restrict__ QLh, const __nv_bfloat16* __restrict__ QLl,
        const __nv_bfloat16* __restrict__ KLh, const __nv_bfloat16* __restrict__ KLl,
        unsigned* __restrict__ rowparts, unsigned* __restrict__ colparts) {
    extern __shared__ char smem[];
    float (*Ct)[130] = (float(*)[130])smem;
    int tid = threadIdx.x;
    int wid = tid >> 5, lane = tid & 31;
    int m0 = blockIdx.y * 128, n0 = blockIdx.x * 128;
    int wm0 = (wid >> 2) * 64, wn0 = (wid & 3) * 32;

    int a_row = wm0 + (lane & 15);
    int a_ch  = (lane >> 4);
    int b_row = wn0 + (lane & 7);
    int b_ch  = ((lane >> 3) & 1);
    uint32_t smem_b = smem_u32(smem);

    float d[4][4][4];
    #pragma unroll
    for (int i = 0; i < 4; i++)
        #pragma unroll
        for (int j = 0; j < 4; j++)
            #pragma unroll
            for (int q = 0; q < 4; q++) d[i][j][q] = 0.f;

    auto stage = [&](int kc, int buf) {
        uint32_t b0 = smem_b + buf * PK_BUF;
        #pragma unroll
        for (int t = 0; t < 4; t++) {
            int s2 = tid + t * 256;
            int row = s2 >> 3, sc = s2 & 7;
            uint32_t sw = SWZ128((uint32_t)(row * 128 + sc * 16));
            long ga = (long)(m0 + row) * 512 + kc * 64 + sc * 8;
            long gb = (long)(n0 + row) * 512 + kc * 64 + sc * 8;
            cp_async16(b0 + SM_AH + sw, QLh + ga);
            cp_async16(b0 + SM_AL + sw, QLl + ga);
            cp_async16(b0 + SM_BH + sw, KLh + gb);
            cp_async16(b0 + SM_BL + sw, KLl + gb);
        }
        cp_commit();
    };

    stage(0, 0);
    for (int kc = 0; kc < 8; kc++) {
        if (kc < 7) stage(kc + 1, (kc + 1) & 1);
        if (kc < 7) cp_wait<1>(); else cp_wait<0>();
        __syncthreads();
        uint32_t bofs = (uint32_t)((kc & 1) * PK_BUF);

        #pragma unroll
        for (int ks = 0; ks < 4; ks++) {
            int ach = (ks * 2 + a_ch) ^ (a_row & 7);
            int bch = (ks * 2 + b_ch) ^ (b_row & 7);
            uint32_t ah[4][4], bh[4][2], bl[4][2], al[4][4];
            #pragma unroll
            for (int i = 0; i < 4; i++)
                ldsm_x4(ah[i], smem_b + bofs + SM_AH + (a_row + i * 16) * 128 + ach * 16);
            #pragma unroll
            for (int j = 0; j < 4; j++)
                ldsm_x2(bh[j], smem_b + bofs + SM_BH + (b_row + j * 8) * 128 + bch * 16);
            #pragma unroll
            for (int i = 0; i < 4; i++)
                #pragma unroll
                for (int j = 0; j < 4; j++) mma_bf16(d[i][j], ah[i], bh[j]);
            #pragma unroll
            for (int j = 0; j < 4; j++)
                ldsm_x2(bl[j], smem_b + bofs + SM_BL + (b_row + j * 8) * 128 + bch * 16);
            #pragma unroll
            for (int i = 0; i < 4; i++)
                #pragma unroll
                for (int j = 0; j < 4; j++) mma_bf16(d[i][j], ah[i], bl[j]);
            #pragma unroll
            for (int i = 0; i < 4; i++)
                ldsm_x4(al[i], smem_b + bofs + SM_AL + (a_row + i * 16) * 128 + ach * 16);
            #pragma unroll
            for (int i = 0; i < 4; i++)
                #pragma unroll
                for (int j = 0; j < 4; j++) mma_bf16(d[i][j], al[i], bh[j]);
        }
        __syncthreads();
    }

    int fr = lane >> 2, fc = (lane & 3) * 2;
    #pragma unroll
    for (int i = 0; i < 4; i++) {
        #pragma unroll
        for (int j = 0; j < 4; j++) {
            int r = wm0 + i * 16 + fr, c = wn0 + j * 8 + fc;
            *(float2*)&Ct[r][c]     = make_float2(d[i][j][0], d[i][j][1]);
            *(float2*)&Ct[r + 8][c] = make_float2(d[i][j][2], d[i][j][3]);
        }
    }
    __syncthreads();

    if (tid < 128) {
        int r = tid, gr = m0 + r;
        int b0 = n0 / 196;
        int bnd = (b0 + 1) * 196 - n0;
        if (bnd > 128) bnd = 128;
        float m1 = -INFINITY, m2 = -INFINITY;
        for (int c = 0; c < 128; c++) {
            float v = Ct[r][c];
            if (c < bnd) m1 = fmaxf(m1, v); else m2 = fmaxf(m2, v);
        }
        atomicMax(&rowparts[b0 * 6272 + gr], enc_f(m1));
        if (bnd < 128)
            atomicMax(&rowparts[(b0 + 1) * 6272 + gr], enc_f(m2));
    } else {
        int c = tid - 128, gc = n0 + c;
        int a0 = m0 / 196;
        int bnd = (a0 + 1) * 196 - m0;
        if (bnd > 128) bnd = 128;
        float m1 = -INFINITY, m2 = -INFINITY;
        for (int r = 0; r < 128; r++) {
            float v = Ct[r][c];
            if (r < bnd) m1 = fmaxf(m1, v); else m2 = fmaxf(m2, v);
        }
        atomicMax(&colparts[a0 * 6272 + gc], enc_f(m1));
        if (bnd < 128)
            atomicMax(&colparts[(a0 + 1) * 6272 + gc], enc_f(m2));
    }
}

// ---------------------------------------------------------------------------
__global__ void reduce_s_kernel(const unsigned* __restrict__ rowparts,
                                const unsigned* __restrict__ colparts,
                                const float* __restrict__ logit_scale,
                                float* __restrict__ S) {
    int pair = blockIdx.x, tid = threadIdx.x;
    int a = pair >> 5, b = pair & 31;
    float s = 0.f;
    for (int l = tid; l < 196; l += 256)
        s += dec_f(rowparts[b * 6272 + a * 196 + l]);
    for (int m = tid; m < 196; m += 256)
        s += dec_f(colparts[a * 6272 + b * 196 + m]);
    __shared__ float red[256];
    red[tid] = s;
    __syncthreads();
    for (int st = 128; st; st >>= 1) {
        if (tid < st) red[tid] += red[tid + st];
        __syncthreads();
    }
    if (tid == 0) S[pair] = 0.5f * red[0] * (1.f / 196.f) * expf(logit_scale[0]);
}

__global__ void loss_kernel(const float* __restrict__ S, float* __restrict__ out) {
    int tid = threadIdx.x;
    int w = tid >> 5, lane = tid & 31;
    float rv = S[w * 32 + lane];
    float cv = S[lane * 32 + w];
    float rm = rv, cm = cv;
    #pragma unroll
    for (int off = 16; off; off >>= 1) {
        rm = fmaxf(rm, __shfl_xor_sync(0xffffffffu, rm, off));
        cm = fmaxf(cm, __shfl_xor_sync(0xffffffffu, cm, off));
    }
    float re = expf(rv - rm), cex = expf(cv - cm);
    #pragma unroll
    for (int off = 16; off; off >>= 1) {
        re  += __shfl_xor_sync(0xffffffffu, re, off);
        cex += __shfl_xor_sync(0xffffffffu, cex, off);
    }
    __shared__ float acc[32];
    if (lane == 0) {
        float dg = S[w * 33];
        acc[w] = (dg - (rm + logf(re))) + (dg - (cm + logf(cex)));
    }
    __syncthreads();
    if (tid == 0) {
        float t = 0.f;
        for (int i = 0; i < 32; i++) t += acc[i];
        out[0] = -0.5f * t * (1.f / 32.f);
    }
}

// ---------------------------------------------------------------------------
extern "C" void kernel_launch(void* const* d_in, const int* in_sizes, int n_in,
                              void* d_out, int out_size) {
    const float* bef        = (const float*)d_in[0];
    const float* sentf      = (const float*)d_in[1];
    const float* aft        = (const float*)d_in[2];
    const float* masks      = (const float*)d_in[3];
    const float* conv1_w    = (const float*)d_in[4];
    const float* conv1_b    = (const float*)d_in[5];
    const float* in_proj_w  = (const float*)d_in[6];
    const float* out_proj_w = (const float*)d_in[7];
    const float* conv2_w    = (const float*)d_in[8];
    const float* conv2_b    = (const float*)d_in[9];
    const float* q_w        = (const float*)d_in[10];
    const float* q_b        = (const float*)d_in[11];
    const float* k_w        = (const float*)d_in[12];
    const float* k_b        = (const float*)d_in[13];
    const float* logit_scale= (const float*)d_in[14];

    float* base = nullptr;
    cudaGetSymbolAddress((void**)&base, g_buf);
    float* p_sm  = base + OFF_SM;
    float* p_b2  = base + OFF_B2;
    float* p_bq  = base + OFF_BQ;
    float* p_w67 = base + OFF_W67;
    float* p_wq  = base + OFF_WQ;
    float* p_S   = base + OFF_S;
    float* p_v1  = base + OFF_V1;
    float* p_qkv = base + OFF_QKV;
    unsigned* p_rp = (unsigned*)(base + OFF_RP);
    unsigned* p_cp = (unsigned*)(base + OFF_CP);
    #define BF16P(off) ((__nv_bfloat16*)(base + (off)))
    __nv_bfloat16* aoh  = BF16P(OFF_AOH);  __nv_bfloat16* aol  = BF16P(OFF_AOL);
    __nv_bfloat16* afth = BF16P(OFF_AFTH); __nv_bfloat16* aftl = BF16P(OFF_AFTL);
    __nv_bfloat16* qlh  = BF16P(OFF_QLH);  __nv_bfloat16* qll  = BF16P(OFF_QLL);
    __nv_bfloat16* klh  = BF16P(OFF_KLH);  __nv_bfloat16* kll  = BF16P(OFF_KLL);
    __nv_bfloat16* wqh  = BF16P(OFF_WQH);  __nv_bfloat16* wql  = BF16P(OFF_WQL);
    __nv_bfloat16* kwh  = BF16P(OFF_KWH);  __nv_bfloat16* kwl  = BF16P(OFF_KWL);

    cudaFuncSetAttribute(mma_gemm_b1, cudaFuncAttributeMaxDynamicSharedMemorySize, MG_SMEM);
    cudaFuncSetAttribute(pair_mma_kernel, cudaFuncAttributeMaxDynamicSharedMemorySize, PK_SMEM);

    // prep: text mean, per-batch conv1 bias, init partials, aft/k_w splits
    sent_mean_kernel<<<32, 512>>>(sentf, masks, p_sm);
    bias2_kernel<<<2048, 256>>>(conv1_w, conv1_b, p_sm, p_b2);
    init_parts_kernel<<<256, 256>>>(p_rp, 2 * 200704);
    split_vec_kernel<<<512, 256>>>((const float4*)aft, (uint2*)afth, (uint2*)aftl, 6272 * 128);
    split_vec_kernel<<<256, 256>>>((const float4*)k_w, (uint2*)kwh, (uint2*)kwl, 512 * 128);

    // v1 = bef @ conv1_w[:, :512]^T + bias2[b]   (exact fp32)
    gemm128<2><<<dim3(4, 49), 256>>>(bef, conv1_w, p_v1, p_b2, 512, 512, 1024, 512);
    // qkv = v1 @ in_proj_w^T                     (exact fp32)
    gemm128<0><<<dim3(12, 49), 256>>>(p_v1, in_proj_w, p_qkv, nullptr, 512, 512, 512, 1536);

    size_t attn_smem = (2 * 196 * 65 + 8 * 256) * sizeof(float);
    cudaFuncSetAttribute(attn_kernel, cudaFuncAttributeMaxDynamicSharedMemorySize, (int)attn_smem);
    attn_kernel<<<256, 256, attn_smem>>>(p_qkv, aoh, aol);

    // fused weights: Wq = q_w @ conv2_w @ out_proj_w ; bq = q_b + q_w@conv2_b
    gemm64_nt<<<dim3(8, 8), 256>>>(conv2_w, out_proj_w, p_w67, 512, 512, 512, 512);
    gemm64_nt<<<dim3(8, 8), 256>>>(q_w, p_w67, p_wq, 512, 512, 512, 512);
    bq_kernel<<<64, 256>>>(q_w, conv2_b, q_b, p_bq);
    split_vec_kernel<<<256, 256>>>((const float4*)p_wq, (uint2*)wqh, (uint2*)wql, 512 * 128);

    // QL = ao @ Wq^T + bq ; KL = aft @ k_w^T + k_b   (bf16x3 mma, split out)
    mma_gemm_b1<<<dim3(4, 49), 256, MG_SMEM>>>(aoh, aol, wqh, wql, qlh, qll, p_bq);
    mma_gemm_b1<<<dim3(4, 49), 256, MG_SMEM>>>(afth, aftl, kwh, kwl, klh, kll, k_b);

    // pair GEMM + fused max epilogue (cp.async double-buffered)
    pair_mma_kernel<<<dim3(49, 49), 256, PK_SMEM>>>(qlh, qll, klh, kll, p_rp, p_cp);

    reduce_s_kernel<<<1024, 256>>>(p_rp, p_cp, logit_scale, p_S);
    loss_kernel<<<1, 1024>>>(p_S, (float*)d_out);
}